// round 13
// baseline (speedup 1.0000x reference)
#include <cuda_runtime.h>
#include <cuda_fp16.h>
#include <math.h>
#include <stdint.h>

#define TOK 512
#define DMODEL 512
#define FF 2048
#define DN 128
#define DH 256
#define DH2 512
#define LN_EPS 1e-5f
#define NNODES 32

// ---------------- scratch (no allocation allowed) ----------------
__device__ float g_acts[TOK * FF];
__device__ float g_nvproj[FF * DH];
__device__ float g_aggT[DH * TOK];          // [k][t]
__device__ float g_c0[DH];
__device__ float g_r[TOK * DH];
__device__ float g_r2[TOK * DH2];
__device__ __align__(16) __half g_w2f16[4][256 * 72];
__device__ __align__(16) __half g_xf16[TOK * DMODEL];
__device__ __align__(16) __half g_wf16[FF * DMODEL];
__device__ float4 g_fc[FF];                 // per-f LN1 constants
__device__ float g_wscal[2];
__device__ float g_cf[FF];                  // a-range center
__device__ float g_hf[FF];                  // a-range half width
__device__ float g_ihf[FF];                 // 1 / half width
__device__ __align__(16) __half g_cT[DH * FF * NNODES];    // [k][f*32+j]

__device__ __forceinline__ float gelu_exact(float x) {
    return 0.5f * x * (1.0f + erff(x * 0.70710678118654752440f));
}

__device__ __forceinline__ uint32_t smem_to_u32(const void* p) {
    uint32_t a;
    asm("{ .reg .u64 t; cvta.to.shared.u64 t, %1; cvt.u32.u64 %0, t; }"
        : "=r"(a) : "l"(p));
    return a;
}

__device__ __forceinline__ uint32_t pack_f16(float e0, float e1) {
    uint32_t r;  // e0 -> low half
    asm("cvt.rn.f16x2.f32 %0, %1, %2;" : "=r"(r) : "f"(e1), "f"(e0));
    return r;
}

#define LDSM_X4(r0, r1, r2, r3, addr) \
    asm volatile("ldmatrix.sync.aligned.m8n8.x4.shared.b16 {%0,%1,%2,%3}, [%4];" \
        : "=r"(r0), "=r"(r1), "=r"(r2), "=r"(r3) : "r"(addr))
#define LDSM_X2(r0, r1, addr) \
    asm volatile("ldmatrix.sync.aligned.m8n8.x2.shared.b16 {%0,%1}, [%2];" \
        : "=r"(r0), "=r"(r1) : "r"(addr))
#define MMA16816F16(d, a, b) \
    asm volatile("mma.sync.aligned.m16n8k16.row.col.f32.f16.f16.f32 " \
        "{%0,%1,%2,%3}, {%4,%5,%6,%7}, {%8,%9}, {%0,%1,%2,%3};" \
        : "+f"((d)[0]), "+f"((d)[1]), "+f"((d)[2]), "+f"((d)[3]) \
        : "r"((a)[0]), "r"((a)[1]), "r"((a)[2]), "r"((a)[3]), \
          "r"((b)[0]), "r"((b)[1]))
#define CP_ASYNC16(dst, src) \
    asm volatile("cp.async.cg.shared.global [%0], [%1], 16;" \
        :: "r"(dst), "l"(src) : "memory")
#define CP_COMMIT() asm volatile("cp.async.commit_group;" ::: "memory")
#define CP_WAIT(n)  asm volatile("cp.async.wait_group %0;" :: "n"(n) : "memory")

// ======================= generic SIMT GEMM (small stages) ==================
template <bool GELU, bool BIAS>
__device__ __forceinline__ void gemm_tn_body(
    const float* __restrict__ A, int lda,
    const float* __restrict__ B, int ldb,
    const float* __restrict__ bias,
    float* __restrict__ C, int ldc, int K)
{
    constexpr int BM = 64, BN = 128, BK = 32;
    __shared__ float sA[BK][BM + 2];
    __shared__ float sB[BK][BN + 2];
    int tid = threadIdx.x;
    int lane = tid & 31, wid = tid >> 5;
    int bm = blockIdx.x * BM, bn = blockIdx.y * BN;

    float acc[8][4];
#pragma unroll
    for (int i = 0; i < 8; i++)
#pragma unroll
        for (int u = 0; u < 4; u++) acc[i][u] = 0.f;

    for (int k0 = 0; k0 < K; k0 += BK) {
#pragma unroll
        for (int r = 0; r < 8; r++) {
            int m = wid + 8 * r;
            sA[lane][m] = A[(size_t)(bm + m) * lda + k0 + lane];
        }
#pragma unroll
        for (int r = 0; r < 16; r++) {
            int n = wid + 8 * r;
            sB[lane][n] = B[(size_t)(bn + n) * ldb + k0 + lane];
        }
        __syncthreads();
#pragma unroll
        for (int kk = 0; kk < BK; kk++) {
            float a[8], b[4];
#pragma unroll
            for (int i = 0; i < 8; i++) a[i] = sA[kk][wid * 8 + i];
#pragma unroll
            for (int u = 0; u < 4; u++) b[u] = sB[kk][lane + 32 * u];
#pragma unroll
            for (int i = 0; i < 8; i++)
#pragma unroll
                for (int u = 0; u < 4; u++) acc[i][u] += a[i] * b[u];
        }
        __syncthreads();
    }
#pragma unroll
    for (int i = 0; i < 8; i++) {
        int m = bm + wid * 8 + i;
#pragma unroll
        for (int u = 0; u < 4; u++) {
            int n = bn + lane + 32 * u;
            float v = acc[i][u];
            if (BIAS) v += bias[n];
            if (GELU) v = gelu_exact(v);
            C[(size_t)m * ldc + n] = v;
        }
    }
}

__global__ void __launch_bounds__(256) gemm_nvproj(const float* __restrict__ nv,
                                                   const float* __restrict__ phi_w1)
{   gemm_tn_body<false, false>(nv, DN, phi_w1, DN + 1, nullptr, g_nvproj, DH, DN); }

__global__ void __launch_bounds__(256) gemm_rho1(const float* __restrict__ rho_w1,
                                                 const float* __restrict__ rho_b1)
{   gemm_tn_body<true, true>(g_r, DH, rho_w1, DH, rho_b1, g_r2, DH2, DH); }

__global__ void __launch_bounds__(256) gemm_rho2(const float* __restrict__ rho_w2,
                                                 const float* __restrict__ rho_b2,
                                                 float* __restrict__ out)
{   gemm_tn_body<false, true>(g_r2, DH2, rho_w2, DH2, rho_b2, out, DMODEL, DH2); }

// ======================= fused convert prep =======================
__global__ void __launch_bounds__(256) prep_conv(const float* __restrict__ x,
                                                 const float* __restrict__ W_in,
                                                 const float* __restrict__ w2) {
    int idx = blockIdx.x * 256 + threadIdx.x;
    if (idx < TOK * DMODEL) g_xf16[idx] = __float2half(x[idx]);
    int i2 = idx - TOK * DMODEL;
    if (i2 >= 0 && i2 < FF * DMODEL) g_wf16[i2] = __float2half(W_in[i2]);
    int i3 = i2 - FF * DMODEL;
    if (i3 >= 0 && i3 < DH * DH) {
        int j = i3 >> 8, k = i3 & 255;
        int kc = k >> 6, kin = k & 63;
        g_w2f16[kc][j * 72 + kin] = __float2half(w2[i3]);
    }
}

// ======================= fp16 tensor acts GEMM =====================
constexpr int GA_A_BUF = 9216;    // 64 x 144
constexpr int GA_B_OFF = 18432;
constexpr int GA_B_BUF = 18432;   // 128 x 144
constexpr int GA_SMEM  = 55296;

__global__ void __launch_bounds__(256) gemm_acts_f16() {
    extern __shared__ char smem[];
    const uint32_t sbase = smem_to_u32(smem);
    const int tid = threadIdx.x, lane = tid & 31, wid = tid >> 5;
    const int bm = blockIdx.x * 64, bn = blockIdx.y * 128;
    const int wm = wid & 1, wn = wid >> 1;

    auto loadA = [&](int kc, int buf) {
        uint32_t dst = sbase + buf * GA_A_BUF;
#pragma unroll
        for (int q = 0; q < 2; q++) {
            int i2 = tid + q * 256;
            int row = i2 >> 3, seg = i2 & 7;
            const char* src = (const char*)(g_xf16 +
                (size_t)(bm + row) * DMODEL + kc * 64 + seg * 8);
            CP_ASYNC16(dst + row * 144 + seg * 16, src);
        }
    };
    auto loadB = [&](int kc, int buf) {
        uint32_t dst = sbase + GA_B_OFF + buf * GA_B_BUF;
#pragma unroll
        for (int q = 0; q < 4; q++) {
            int i2 = tid + q * 256;
            int row = i2 >> 3, seg = i2 & 7;
            const char* src = (const char*)(g_wf16 +
                (size_t)(bn + row) * DMODEL + kc * 64 + seg * 8);
            CP_ASYNC16(dst + row * 144 + seg * 16, src);
        }
    };

    float acc[2][4][4];
#pragma unroll
    for (int mt = 0; mt < 2; mt++)
#pragma unroll
        for (int nt = 0; nt < 4; nt++)
#pragma unroll
            for (int i = 0; i < 4; i++) acc[mt][nt][i] = 0.f;

    const uint32_t aBase0 = sbase +
        (uint32_t)((wm * 32 + (lane & 15)) * 144 + (lane >> 4) * 16);
    const uint32_t bBase0 = sbase + GA_B_OFF +
        (uint32_t)((wn * 32 + (lane & 7)) * 144 + ((lane >> 3) & 1) * 16);

    loadA(0, 0); loadB(0, 0); CP_COMMIT();
#pragma unroll 1
    for (int kc = 0; kc < 8; kc++) {
        if (kc < 7) {
            loadA(kc + 1, (kc + 1) & 1);
            loadB(kc + 1, (kc + 1) & 1);
            CP_COMMIT();
            CP_WAIT(1);
        } else {
            CP_WAIT(0);
        }
        __syncthreads();
        const uint32_t aB = aBase0 + (kc & 1) * GA_A_BUF;
        const uint32_t bC = bBase0 + (kc & 1) * GA_B_BUF;
#pragma unroll
        for (int k16 = 0; k16 < 4; k16++) {
            const uint32_t koff = k16 * 32;
            uint32_t ah[2][4], bb[4][2];
#pragma unroll
            for (int mt = 0; mt < 2; mt++)
                LDSM_X4(ah[mt][0], ah[mt][1], ah[mt][2], ah[mt][3],
                        aB + mt * 2304 + koff);
#pragma unroll
            for (int nt = 0; nt < 4; nt++)
                LDSM_X2(bb[nt][0], bb[nt][1], bC + nt * 1152 + koff);
#pragma unroll
            for (int mt = 0; mt < 2; mt++)
#pragma unroll
                for (int nt = 0; nt < 4; nt++)
                    MMA16816F16(acc[mt][nt], ah[mt], bb[nt]);
        }
        __syncthreads();
    }

#pragma unroll
    for (int mt = 0; mt < 2; mt++) {
#pragma unroll
        for (int h = 0; h < 2; h++) {
            int m = bm + wm * 32 + mt * 16 + (lane >> 2) + 8 * h;
#pragma unroll
            for (int nt = 0; nt < 4; nt++) {
                int n = bn + wn * 32 + nt * 8 + (lane & 3) * 2;
                float v0 = gelu_exact(acc[mt][nt][2 * h]);
                float v1 = gelu_exact(acc[mt][nt][2 * h + 1]);
                *(float2*)&g_acts[(size_t)m * FF + n] = make_float2(v0, v1);
            }
        }
    }
}

// ======================= prep kernels =======================
__global__ void __launch_bounds__(256) prep_f(const float* __restrict__ phi_b1,
                                              const float* __restrict__ phi_w1) {
    int f = blockIdx.x;
    int tid = threadIdx.x, lane = tid & 31, wid = tid >> 5;
    float w = phi_w1[tid * (DN + 1) + DN];
    if (f == FF) {
        float s0 = w, s1 = w * w;
#pragma unroll
        for (int o = 16; o; o >>= 1) {
            s0 += __shfl_xor_sync(~0u, s0, o);
            s1 += __shfl_xor_sync(~0u, s1, o);
        }
        __shared__ float r0[8], r1[8];
        if (lane == 0) { r0[wid] = s0; r1[wid] = s1; }
        __syncthreads();
        if (tid == 0) {
            float t0 = 0.f, t1 = 0.f;
            for (int i = 0; i < 8; i++) { t0 += r0[i]; t1 += r1[i]; }
            g_wscal[0] = t0 * (1.f / DH);
            g_wscal[1] = t1 * (1.f / DH);
        }
        return;
    }
    float p = g_nvproj[f * DH + tid] + phi_b1[tid];
    float s0 = p, s1 = p * p, s2 = p * w;
#pragma unroll
    for (int o = 16; o; o >>= 1) {
        s0 += __shfl_xor_sync(~0u, s0, o);
        s1 += __shfl_xor_sync(~0u, s1, o);
        s2 += __shfl_xor_sync(~0u, s2, o);
    }
    __shared__ float r0[8], r1[8], r2[8];
    if (lane == 0) { r0[wid] = s0; r1[wid] = s1; r2[wid] = s2; }
    __syncthreads();
    if (tid == 0) {
        float t0 = 0.f, t1 = 0.f, t2 = 0.f;
        for (int i = 0; i < 8; i++) { t0 += r0[i]; t1 += r1[i]; t2 += r2[i]; }
        g_fc[f] = make_float4(t0 * (1.f / DH), t1 * (1.f / DH), t2 * (1.f / DH), 0.f);
    }
}

// blocks [0,FF): per-f a-range; rest: zero aggT/c0
__global__ void __launch_bounds__(256) range_zero() {
    int tid = threadIdx.x;
    int bid = blockIdx.x;
    if (bid < FF) {
        int f = bid;
        float v0 = g_acts[(size_t)tid * FF + f];
        float v1 = g_acts[(size_t)(tid + 256) * FF + f];
        float mn = fminf(v0, v1), mx = fmaxf(v0, v1);
#pragma unroll
        for (int o = 16; o; o >>= 1) {
            mn = fminf(mn, __shfl_xor_sync(~0u, mn, o));
            mx = fmaxf(mx, __shfl_xor_sync(~0u, mx, o));
        }
        __shared__ float smn[8], smx[8];
        int lane = tid & 31, wid = tid >> 5;
        if (lane == 0) { smn[wid] = mn; smx[wid] = mx; }
        __syncthreads();
        if (tid == 0) {
            float a = smn[0], b = smx[0];
#pragma unroll
            for (int i = 1; i < 8; i++) { a = fminf(a, smn[i]); b = fmaxf(b, smx[i]); }
            float c = 0.5f * (b + a), h = 0.5f * (b - a) + 1e-6f;
            g_cf[f] = c; g_hf[f] = h; g_ihf[f] = 1.0f / h;
        }
    } else {
        int i = (bid - FF) * 256 + tid;
        if (i < DH * TOK) g_aggT[i] = 0.f;
        if (i < DH) g_c0[i] = 0.f;
    }
}

// ======================= node evaluation + fused DCT =====================
// block = 4 neurons x 32 nodes (M rows: row = fi*32 + s). After LN2, z is
// staged fp16 in smem and DCT'd in-block -> g_cT directly. No znodes buffer.
constexpr int CONST_B1   = 0;
constexpr int CONST_WACT = 256;
constexpr int CONST_L1G  = 512;
constexpr int CONST_L1B  = 768;
constexpr int CONST_B2   = 1024;
constexpr int CONST_L2G  = 1280;
constexpr int CONST_L2B  = 1536;
constexpr int SR1_OFF    = 1792;
constexpr int SR2_OFF    = 2304;
constexpr int SMU_OFF    = 2816;
constexpr int SIS_OFF    = 2944;
constexpr int A_OFF      = 12288;
constexpr int A_BUF      = 18432;
constexpr int B_OFF      = A_OFF + 2 * A_BUF;
constexpr int B_CHUNK    = 36864;
constexpr int NE_SMEM    = B_OFF + 4 * B_CHUNK;   // 196608
constexpr int ZB_PITCH   = 272;                   // halves per row (pad)

__global__ void __launch_bounds__(256, 1) node_eval(
    const float* __restrict__ phi_b1, const float* __restrict__ phi_w1,
    const float* __restrict__ ln1g, const float* __restrict__ ln1b,
    const float* __restrict__ b2, const float* __restrict__ ln2g,
    const float* __restrict__ ln2b)
{
    extern __shared__ char smem[];
    float* sF = (float*)smem;
    const uint32_t sbase = smem_to_u32(smem);

    const int tid = threadIdx.x, lane = tid & 31, wid = tid >> 5;
    const int fbase4 = blockIdx.x * 4;

    {
        uint32_t dst = sbase + B_OFF + tid * 16;
        const char* src = (const char*)g_w2f16 + tid * 16;
#pragma unroll
        for (int i = 0; i < 36; i++)
            CP_ASYNC16(dst + i * 4096, src + i * 4096);
        CP_COMMIT();
    }

    sF[CONST_B1 + tid]   = phi_b1[tid];
    sF[CONST_WACT + tid] = phi_w1[tid * (DN + 1) + DN];
    sF[CONST_L1G + tid]  = ln1g[tid];
    sF[CONST_L1B + tid]  = ln1b[tid];
    sF[CONST_B2 + tid]   = b2[tid];
    sF[CONST_L2G + tid]  = ln2g[tid];
    sF[CONST_L2B + tid]  = ln2b[tid];
    __syncthreads();

    const int g = wid >> 2, wn = wid & 3;
    const int wg_tid = tid & 127;

    // produce mapping: block row = g*64 + (wg_tid>>1); f = fbase4 + row>>5
    const int prow = g * 64 + (wg_tid >> 1);
    const int khalf = wg_tid & 1;
    const int f = fbase4 + (prow >> 5);
    const int snode = prow & 31;
    const float xs = cospif((float)(2 * snode + 1) / (2.0f * NNODES));
    const float a = g_cf[f] + g_hf[f] * xs;
    const float4 fc = g_fc[f];
    const float mean = fc.x + a * g_wscal[0];
    const float e2 = fc.y + 2.f * a * fc.z + a * a * g_wscal[1];
    const float istd = rsqrtf(e2 - mean * mean + LN_EPS);
    const float nmi = -mean * istd;

    char* const aDst0 = smem + A_OFF + prow * 144 + khalf * 64;
    const float* const nvRow = g_nvproj + (size_t)f * DH + khalf * 32;

    auto produce = [&](int kc, int buf) {
        const float* nvp = nvRow + kc * 64;
        char* aDst = aDst0 + buf * A_BUF;
#pragma unroll 2
        for (int u = 0; u < 8; u++) {
            float4 pv = *(const float4*)(nvp + u * 4);
            float p4[4] = {pv.x, pv.y, pv.z, pv.w};
            float gv[4];
            int kb = kc * 64 + khalf * 32 + u * 4;
#pragma unroll
            for (int e = 0; e < 4; e++) {
                int k = kb + e;
                float val = fmaf(a, sF[CONST_WACT + k], p4[e] + sF[CONST_B1 + k]);
                float sc = fmaf(val, istd, nmi);
                float xx = fmaf(sc, sF[CONST_L1G + k], sF[CONST_L1B + k]);
                gv[e] = gelu_exact(xx);
            }
            *(uint2*)(aDst + u * 8) =
                make_uint2(pack_f16(gv[0], gv[1]), pack_f16(gv[2], gv[3]));
        }
    };

    float acc[4][8][4];
#pragma unroll
    for (int mt = 0; mt < 4; mt++)
#pragma unroll
        for (int nt = 0; nt < 8; nt++)
#pragma unroll
            for (int i = 0; i < 4; i++) acc[mt][nt][i] = 0.f;

    const uint32_t aBase0 = sbase + A_OFF + g * 9216 +
        (uint32_t)((lane & 15) * 144 + (lane >> 4) * 16);
    const uint32_t bBase = sbase + B_OFF +
        (uint32_t)((wn * 64 + (lane & 7)) * 144 + ((lane >> 3) & 1) * 16);

    auto mma_chunk = [&](int kc) {
        const uint32_t aB = aBase0 + (kc & 1) * A_BUF;
        const uint32_t bC = bBase + kc * B_CHUNK;
#pragma unroll
        for (int k16 = 0; k16 < 4; k16++) {
            const uint32_t koff = k16 * 32;
            uint32_t ah[4][4], bb[8][2];
#pragma unroll
            for (int mt = 0; mt < 4; mt++)
                LDSM_X4(ah[mt][0], ah[mt][1], ah[mt][2], ah[mt][3],
                        aB + mt * 2304 + koff);
#pragma unroll
            for (int nt = 0; nt < 8; nt++)
                LDSM_X2(bb[nt][0], bb[nt][1], bC + nt * 1152 + koff);
#pragma unroll
            for (int mt = 0; mt < 4; mt++)
#pragma unroll
                for (int nt = 0; nt < 8; nt++)
                    MMA16816F16(acc[mt][nt], ah[mt], bb[nt]);
        }
    };

    produce(0, 0);
    CP_WAIT(0);
    __syncthreads();
#pragma unroll
    for (int kc = 0; kc < 4; kc++) {
        mma_chunk(kc);
        if (kc < 3) produce(kc + 1, (kc + 1) & 1);
        __syncthreads();
    }

    // ---- epilogue: LN2 stats ----
    float b2c[16], gc[16], bc[16];
#pragma unroll
    for (int nt = 0; nt < 8; nt++) {
        int j0 = wn * 64 + nt * 8 + (lane & 3) * 2;
        b2c[2 * nt]     = sF[CONST_B2 + j0];
        b2c[2 * nt + 1] = sF[CONST_B2 + j0 + 1];
        gc[2 * nt]      = sF[CONST_L2G + j0];
        gc[2 * nt + 1]  = sF[CONST_L2G + j0 + 1];
        bc[2 * nt]      = sF[CONST_L2B + j0];
        bc[2 * nt + 1]  = sF[CONST_L2B + j0 + 1];
    }

#pragma unroll
    for (int mt = 0; mt < 4; mt++) {
#pragma unroll
        for (int h = 0; h < 2; h++) {
            float s1 = 0.f, s2 = 0.f;
#pragma unroll
            for (int nt = 0; nt < 8; nt++) {
                float y0 = acc[mt][nt][2 * h]     + b2c[2 * nt];
                float y1 = acc[mt][nt][2 * h + 1] + b2c[2 * nt + 1];
                acc[mt][nt][2 * h]     = y0;
                acc[mt][nt][2 * h + 1] = y1;
                s1 += y0 + y1;
                s2 += y0 * y0 + y1 * y1;
            }
            s1 += __shfl_xor_sync(~0u, s1, 1);
            s1 += __shfl_xor_sync(~0u, s1, 2);
            s2 += __shfl_xor_sync(~0u, s2, 1);
            s2 += __shfl_xor_sync(~0u, s2, 2);
            if ((lane & 3) == 0) {
                int r = mt * 16 + (lane >> 2) + 8 * h;
                sF[SR1_OFF + g * 256 + r * 4 + wn] = s1;
                sF[SR2_OFF + g * 256 + r * 4 + wn] = s2;
            }
        }
    }
    __syncthreads();
    if (wg_tid < 64) {
        int base = SR1_OFF + g * 256 + wg_tid * 4;
        float s1 = sF[base] + sF[base + 1] + sF[base + 2] + sF[base + 3];
        int base2 = SR2_OFF + g * 256 + wg_tid * 4;
        float s2 = sF[base2] + sF[base2 + 1] + sF[base2 + 2] + sF[base2 + 3];
        float mu = s1 * (1.f / DH);
        float vr = s2 * (1.f / DH) - mu * mu;
        sF[SMU_OFF + g * 64 + wg_tid] = mu;
        sF[SIS_OFF + g * 64 + wg_tid] = rsqrtf(vr + LN_EPS);
    }
    // fill DCT cos matrix into the (dead) A region while waiting
    float* cosm = (float*)(smem + A_OFF);
#pragma unroll
    for (int i = 0; i < 4; i++) {
        int e = tid + i * 256;
        int j = e >> 5, sx = e & 31;
        cosm[e] = cospif((float)(j * (2 * sx + 1)) / (2.0f * NNODES));
    }
    __syncthreads();

    // ---- normalize in fragments, stage z fp16 into dead B region ----
    __half* zb = (__half*)(smem + B_OFF);
#pragma unroll
    for (int mt = 0; mt < 4; mt++) {
#pragma unroll
        for (int h = 0; h < 2; h++) {
            int r = mt * 16 + (lane >> 2) + 8 * h;
            float mu = sF[SMU_OFF + g * 64 + r];
            float is = sF[SIS_OFF + g * 64 + r];
            int grow = g * 64 + r;
#pragma unroll
            for (int nt = 0; nt < 8; nt++) {
                float z0 = (acc[mt][nt][2 * h]     - mu) * is * gc[2 * nt]     + bc[2 * nt];
                float z1 = (acc[mt][nt][2 * h + 1] - mu) * is * gc[2 * nt + 1] + bc[2 * nt + 1];
                int col = wn * 64 + nt * 8 + (lane & 3) * 2;
                *(uint32_t*)&zb[grow * ZB_PITCH + col] = pack_f16(z0, z1);
            }
        }
    }
    __syncthreads();

    // ---- in-block DCT: thread = output k; 4 neurons each ----
    {
        const int k = tid;
        float c0acc = 0.f;
#pragma unroll 1
        for (int fi = 0; fi < 4; fi++) {
            float z[NNODES];
#pragma unroll
            for (int sx = 0; sx < NNODES; sx++)
                z[sx] = __half2float(zb[(fi * 32 + sx) * ZB_PITCH + k]);
            float c0 = 0.f;
#pragma unroll
            for (int sx = 0; sx < NNODES; sx++) c0 += z[sx];
            c0acc += c0 * (1.0f / NNODES);

            float cj[NNODES];
            cj[0] = 0.f;
#pragma unroll
            for (int j = 1; j < NNODES; j++) {
                float c = 0.f;
#pragma unroll
                for (int sx = 0; sx < NNODES; sx++)
                    c = fmaf(z[sx], cosm[j * NNODES + sx], c);
                cj[j] = c * (2.0f / NNODES);
            }
            uint32_t u[NNODES / 2];
#pragma unroll
            for (int i = 0; i < NNODES / 2; i++)
                u[i] = pack_f16(cj[2 * i], cj[2 * i + 1]);
            uint4* dst = (uint4*)(g_cT + (size_t)k * (FF * NNODES) +
                                  (fbase4 + fi) * NNODES);
#pragma unroll
            for (int i = 0; i < 4; i++)
                dst[i] = make_uint4(u[4 * i], u[4 * i + 1], u[4 * i + 2], u[4 * i + 3]);
        }
        atomicAdd(&g_c0[k], c0acc);
    }
}

// ======================= final GEMM: aggT[256,512] = C_T @ T^T ==========
// T computed ON THE FLY from g_acts (Chebyshev recurrence).
constexpr int FG_A0 = 0;
constexpr int FG_A1 = 18432;
constexpr int FG_B0 = 36864;
constexpr int FG_B1 = 73728;
constexpr int FG_SMEM = 110592;
constexpr int KTOT = FF * NNODES;

__global__ void __launch_bounds__(256, 1) gemm_final() {
    extern __shared__ char smem[];
    const uint32_t sbase = smem_to_u32(smem);
    const int tid = threadIdx.x, lane = tid & 31, wid = tid >> 5;
    const int mtile = blockIdx.x & 1;
    const int ntile = (blockIdx.x >> 1) & 1;
    const int ks = blockIdx.x >> 2;
    const int k0 = ks * 2048;
    const int g = wid >> 2, wn = wid & 3;

    auto loadA = [&](int kc, int buf) {
        uint32_t dst = sbase + (buf ? FG_A1 : FG_A0);
#pragma unroll
        for (int q = 0; q < 4; q++) {
            int i2 = tid + q * 256;
            int row = i2 >> 3, seg = i2 & 7;
            const char* src = (const char*)(g_cT +
                (size_t)(mtile * 128 + row) * KTOT + k0 + kc * 64 + seg * 8);
            CP_ASYNC16(dst + row * 144 + seg * 16, src);
        }
    };

    auto produceB = [&](int kc, int buf) {
        char* dstBase = smem + (buf ? FG_B1 : FG_B0);
        const int fbase2 = ks * 64 + kc * 2;
#pragma unroll
        for (int q = 0; q < 2; q++) {
            int p = tid + q * 256;
            int r = p >> 1, fh = p & 1;
            int f = fbase2 + fh;
            float a = g_acts[(size_t)(ntile * 256 + r) * FF + f];
            float x = (a - g_cf[f]) * g_ihf[f];
            x = fminf(1.f, fmaxf(-1.f, x));
            float T[NNODES];
            T[0] = 1.f; T[1] = x;
            float x2 = 2.f * x;
#pragma unroll
            for (int j = 2; j < NNODES; j++) T[j] = fmaf(x2, T[j - 1], -T[j - 2]);
            uint32_t u[NNODES / 2];
#pragma unroll
            for (int i = 0; i < NNODES / 2; i++)
                u[i] = pack_f16(T[2 * i], T[2 * i + 1]);
            char* d = dstBase + r * 144 + fh * 64;
#pragma unroll
            for (int i = 0; i < 4; i++)
                *(uint4*)(d + i * 16) =
                    make_uint4(u[4 * i], u[4 * i + 1], u[4 * i + 2], u[4 * i + 3]);
        }
    };

    float acc[4][8][4];
#pragma unroll
    for (int mt = 0; mt < 4; mt++)
#pragma unroll
        for (int nt = 0; nt < 8; nt++)
#pragma unroll
            for (int i = 0; i < 4; i++) acc[mt][nt][i] = 0.f;

    const uint32_t aBase0 = sbase + FG_A0 +
        (uint32_t)((g * 64 + (lane & 15)) * 144 + (lane >> 4) * 16);
    const uint32_t bBase0 = sbase + FG_B0 +
        (uint32_t)((wn * 64 + (lane & 7)) * 144 + ((lane >> 3) & 1) * 16);

    auto mma_chunk = [&](int kc) {
        const uint32_t aB = aBase0 + (kc & 1) * (FG_A1 - FG_A0);
        const uint32_t bC = bBase0 + (kc & 1) * (FG_B1 - FG_B0);
#pragma unroll
        for (int k16 = 0; k16 < 4; k16++) {
            const uint32_t koff = k16 * 32;
            uint32_t ah[4][4], bb[8][2];
#pragma unroll
            for (int mt = 0; mt < 4; mt++)
                LDSM_X4(ah[mt][0], ah[mt][1], ah[mt][2], ah[mt][3],
                        aB + mt * 2304 + koff);
#pragma unroll
            for (int nt = 0; nt < 8; nt++)
                LDSM_X2(bb[nt][0], bb[nt][1], bC + nt * 1152 + koff);
#pragma unroll
            for (int mt = 0; mt < 4; mt++)
#pragma unroll
                for (int nt = 0; nt < 8; nt++)
                    MMA16816F16(acc[mt][nt], ah[mt], bb[nt]);
        }
    };

    loadA(0, 0); CP_COMMIT();
    produceB(0, 0);
    CP_WAIT(0);
    __syncthreads();
#pragma unroll 1
    for (int kc = 0; kc < 32; kc++) {
        if (kc < 31) { loadA(kc + 1, (kc + 1) & 1); CP_COMMIT(); }
        mma_chunk(kc);
        if (kc < 31) {
            produceB(kc + 1, (kc + 1) & 1);
            CP_WAIT(0);
        }
        __syncthreads();
    }

#pragma unroll
    for (int mt = 0; mt < 4; mt++) {
#pragma unroll
        for (int h = 0; h < 2; h++) {
            int row = mtile * 128 + g * 64 + mt * 16 + (lane >> 2) + 8 * h;
#pragma unroll
            for (int nt = 0; nt < 8; nt++) {
#pragma unroll
                for (int e = 0; e < 2; e++) {
                    int col = ntile * 256 + wn * 64 + nt * 8 + (lane & 3) * 2 + e;
                    atomicAdd(&g_aggT[row * TOK + col], acc[mt][nt][2 * h + e]);
                }
            }
        }
    }
}

// ---------------- final LN over agg (transposed layout + c0) ------------
__global__ void __launch_bounds__(256) ln256_kernel(
    const float* __restrict__ g, const float* __restrict__ b)
{
    int t = blockIdx.x;
    int tid = threadIdx.x;
    int lane = tid & 31, wid = tid >> 5;
    float v = g_aggT[(size_t)tid * TOK + t] + g_c0[tid];
    float s1 = v, s2 = v * v;
#pragma unroll
    for (int o = 16; o; o >>= 1) {
        s1 += __shfl_xor_sync(~0u, s1, o);
        s2 += __shfl_xor_sync(~0u, s2, o);
    }
    __shared__ float r1[8], r2[8];
    if (lane == 0) { r1[wid] = s1; r2[wid] = s2; }
    __syncthreads();
    float t1 = 0.f, t2 = 0.f;
#pragma unroll
    for (int w = 0; w < 8; w++) { t1 += r1[w]; t2 += r2[w]; }
    float mean = t1 * (1.f / DH);
    float var = t2 * (1.f / DH) - mean * mean;
    float istd = rsqrtf(var + LN_EPS);
    g_r[t * DH + tid] = (v - mean) * istd * g[tid] + b[tid];
}

// ---------------- launch ----------------
extern "C" void kernel_launch(void* const* d_in, const int* in_sizes, int n_in,
                              void* d_out, int out_size)
{
    const float* x      = (const float*)d_in[0];
    const float* nv     = (const float*)d_in[1];
    const float* W_in   = (const float*)d_in[2];
    const float* phi_w1 = (const float*)d_in[3];
    const float* phi_b1 = (const float*)d_in[4];
    const float* ln1g   = (const float*)d_in[5];
    const float* ln1b   = (const float*)d_in[6];
    const float* phi_w2 = (const float*)d_in[7];
    const float* phi_b2 = (const float*)d_in[8];
    const float* ln2g   = (const float*)d_in[9];
    const float* ln2b   = (const float*)d_in[10];
    const float* rln_g  = (const float*)d_in[11];
    const float* rln_b  = (const float*)d_in[12];
    const float* rho_w1 = (const float*)d_in[13];
    const float* rho_b1 = (const float*)d_in[14];
    const float* rho_w2 = (const float*)d_in[15];
    const float* rho_b2 = (const float*)d_in[16];
    float* out = (float*)d_out;

    const int conv_total = TOK * DMODEL + FF * DMODEL + DH * DH;
    prep_conv<<<(conv_total + 255) / 256, 256>>>(x, W_in, phi_w2);      // 1

    cudaFuncSetAttribute(gemm_acts_f16,
                         cudaFuncAttributeMaxDynamicSharedMemorySize, GA_SMEM);
    gemm_acts_f16<<<dim3(8, 16), 256, GA_SMEM>>>();                     // 2

    gemm_nvproj<<<dim3(FF / 64, DH / 128), 256>>>(nv, phi_w1);          // 3
    prep_f<<<FF + 1, 256>>>(phi_b1, phi_w1);                            // 4
    range_zero<<<FF + 512, 256>>>();                                    // 5

    cudaFuncSetAttribute(node_eval, cudaFuncAttributeMaxDynamicSharedMemorySize,
                         NE_SMEM);
    node_eval<<<512, 256, NE_SMEM>>>(phi_b1, phi_w1, ln1g, ln1b,
                                     phi_b2, ln2g, ln2b);               // 6

    cudaFuncSetAttribute(gemm_final, cudaFuncAttributeMaxDynamicSharedMemorySize,
                         FG_SMEM);
    gemm_final<<<128, 256, FG_SMEM>>>();                                // 7

    ln256_kernel<<<TOK, 256>>>(rln_g, rln_b);                           // 8
    gemm_rho1<<<dim3(TOK / 64, DH2 / 128), 256>>>(rho_w1, rho_b1);      // 9
    gemm_rho2<<<dim3(TOK / 64, DMODEL / 128), 256>>>(rho_w2, rho_b2, out); // 10

    (void)in_sizes; (void)n_in; (void)out_size;
}

// round 14
// speedup vs baseline: 2.1572x; 2.1572x over previous
#include <cuda_runtime.h>
#include <cuda_fp16.h>
#include <math.h>
#include <stdint.h>

#define TOK 512
#define DMODEL 512
#define FF 2048
#define DN 128
#define DH 256
#define DH2 512
#define LN_EPS 1e-5f
#define NNODES 32

// ---------------- scratch (no allocation allowed) ----------------
__device__ float g_acts[TOK * FF];
__device__ float g_nvproj[FF * DH];
__device__ float g_aggT[DH * TOK];          // [k][t]
__device__ float g_c0[DH];
__device__ float g_r[TOK * DH];
__device__ float g_r2[TOK * DH2];
__device__ __align__(16) __half g_w2f16[4][256 * 72];
__device__ __align__(16) __half g_xf16[TOK * DMODEL];
__device__ __align__(16) __half g_wf16[FF * DMODEL];
__device__ float4 g_fc[FF];                 // per-f LN1 constants
__device__ float g_wscal[2];
__device__ float g_cf[FF];                  // a-range center
__device__ float g_hf[FF];                  // a-range half width
__device__ float g_ihf[FF];                 // 1 / half width
__device__ __align__(16) float g_znodes[FF * NNODES * DH];
__device__ __align__(16) __half g_cT[DH * FF * NNODES];    // [k][f*32+j]

__device__ __forceinline__ float gelu_exact(float x) {
    return 0.5f * x * (1.0f + erff(x * 0.70710678118654752440f));
}

__device__ __forceinline__ uint32_t smem_to_u32(const void* p) {
    uint32_t a;
    asm("{ .reg .u64 t; cvta.to.shared.u64 t, %1; cvt.u32.u64 %0, t; }"
        : "=r"(a) : "l"(p));
    return a;
}

__device__ __forceinline__ uint32_t pack_f16(float e0, float e1) {
    uint32_t r;  // e0 -> low half
    asm("cvt.rn.f16x2.f32 %0, %1, %2;" : "=r"(r) : "f"(e1), "f"(e0));
    return r;
}

#define LDSM_X4(r0, r1, r2, r3, addr) \
    asm volatile("ldmatrix.sync.aligned.m8n8.x4.shared.b16 {%0,%1,%2,%3}, [%4];" \
        : "=r"(r0), "=r"(r1), "=r"(r2), "=r"(r3) : "r"(addr))
#define LDSM_X2(r0, r1, addr) \
    asm volatile("ldmatrix.sync.aligned.m8n8.x2.shared.b16 {%0,%1}, [%2];" \
        : "=r"(r0), "=r"(r1) : "r"(addr))
#define MMA16816F16(d, a, b) \
    asm volatile("mma.sync.aligned.m16n8k16.row.col.f32.f16.f16.f32 " \
        "{%0,%1,%2,%3}, {%4,%5,%6,%7}, {%8,%9}, {%0,%1,%2,%3};" \
        : "+f"((d)[0]), "+f"((d)[1]), "+f"((d)[2]), "+f"((d)[3]) \
        : "r"((a)[0]), "r"((a)[1]), "r"((a)[2]), "r"((a)[3]), \
          "r"((b)[0]), "r"((b)[1]))
#define CP_ASYNC16(dst, src) \
    asm volatile("cp.async.cg.shared.global [%0], [%1], 16;" \
        :: "r"(dst), "l"(src) : "memory")
#define CP_COMMIT() asm volatile("cp.async.commit_group;" ::: "memory")
#define CP_WAIT(n)  asm volatile("cp.async.wait_group %0;" :: "n"(n) : "memory")

// ======================= generic SIMT GEMM (small stages) ==================
template <bool GELU, bool BIAS>
__device__ __forceinline__ void gemm_tn_body(
    const float* __restrict__ A, int lda,
    const float* __restrict__ B, int ldb,
    const float* __restrict__ bias,
    float* __restrict__ C, int ldc, int K)
{
    constexpr int BM = 64, BN = 128, BK = 32;
    __shared__ float sA[BK][BM + 2];
    __shared__ float sB[BK][BN + 2];
    int tid = threadIdx.x;
    int lane = tid & 31, wid = tid >> 5;
    int bm = blockIdx.x * BM, bn = blockIdx.y * BN;

    float acc[8][4];
#pragma unroll
    for (int i = 0; i < 8; i++)
#pragma unroll
        for (int u = 0; u < 4; u++) acc[i][u] = 0.f;

    for (int k0 = 0; k0 < K; k0 += BK) {
#pragma unroll
        for (int r = 0; r < 8; r++) {
            int m = wid + 8 * r;
            sA[lane][m] = A[(size_t)(bm + m) * lda + k0 + lane];
        }
#pragma unroll
        for (int r = 0; r < 16; r++) {
            int n = wid + 8 * r;
            sB[lane][n] = B[(size_t)(bn + n) * ldb + k0 + lane];
        }
        __syncthreads();
#pragma unroll
        for (int kk = 0; kk < BK; kk++) {
            float a[8], b[4];
#pragma unroll
            for (int i = 0; i < 8; i++) a[i] = sA[kk][wid * 8 + i];
#pragma unroll
            for (int u = 0; u < 4; u++) b[u] = sB[kk][lane + 32 * u];
#pragma unroll
            for (int i = 0; i < 8; i++)
#pragma unroll
                for (int u = 0; u < 4; u++) acc[i][u] += a[i] * b[u];
        }
        __syncthreads();
    }
#pragma unroll
    for (int i = 0; i < 8; i++) {
        int m = bm + wid * 8 + i;
#pragma unroll
        for (int u = 0; u < 4; u++) {
            int n = bn + lane + 32 * u;
            float v = acc[i][u];
            if (BIAS) v += bias[n];
            if (GELU) v = gelu_exact(v);
            C[(size_t)m * ldc + n] = v;
        }
    }
}

__global__ void __launch_bounds__(256) gemm_nvproj(const float* __restrict__ nv,
                                                   const float* __restrict__ phi_w1)
{   gemm_tn_body<false, false>(nv, DN, phi_w1, DN + 1, nullptr, g_nvproj, DH, DN); }

__global__ void __launch_bounds__(256) gemm_rho1(const float* __restrict__ rho_w1,
                                                 const float* __restrict__ rho_b1)
{   gemm_tn_body<true, true>(g_r, DH, rho_w1, DH, rho_b1, g_r2, DH2, DH); }

__global__ void __launch_bounds__(256) gemm_rho2(const float* __restrict__ rho_w2,
                                                 const float* __restrict__ rho_b2,
                                                 float* __restrict__ out)
{   gemm_tn_body<false, true>(g_r2, DH2, rho_w2, DH2, rho_b2, out, DMODEL, DH2); }

// ======================= fused convert prep =======================
__global__ void __launch_bounds__(256) prep_conv(const float* __restrict__ x,
                                                 const float* __restrict__ W_in,
                                                 const float* __restrict__ w2) {
    int idx = blockIdx.x * 256 + threadIdx.x;
    if (idx < TOK * DMODEL) g_xf16[idx] = __float2half(x[idx]);
    int i2 = idx - TOK * DMODEL;
    if (i2 >= 0 && i2 < FF * DMODEL) g_wf16[i2] = __float2half(W_in[i2]);
    int i3 = i2 - FF * DMODEL;
    if (i3 >= 0 && i3 < DH * DH) {
        int j = i3 >> 8, k = i3 & 255;
        int kc = k >> 6, kin = k & 63;
        g_w2f16[kc][j * 72 + kin] = __float2half(w2[i3]);
    }
}

// ======================= fp16 tensor acts GEMM =====================
constexpr int GA_A_BUF = 9216;    // 64 x 144
constexpr int GA_B_OFF = 18432;
constexpr int GA_B_BUF = 18432;   // 128 x 144
constexpr int GA_SMEM  = 55296;

__global__ void __launch_bounds__(256) gemm_acts_f16() {
    extern __shared__ char smem[];
    const uint32_t sbase = smem_to_u32(smem);
    const int tid = threadIdx.x, lane = tid & 31, wid = tid >> 5;
    const int bm = blockIdx.x * 64, bn = blockIdx.y * 128;
    const int wm = wid & 1, wn = wid >> 1;

    auto loadA = [&](int kc, int buf) {
        uint32_t dst = sbase + buf * GA_A_BUF;
#pragma unroll
        for (int q = 0; q < 2; q++) {
            int i2 = tid + q * 256;
            int row = i2 >> 3, seg = i2 & 7;
            const char* src = (const char*)(g_xf16 +
                (size_t)(bm + row) * DMODEL + kc * 64 + seg * 8);
            CP_ASYNC16(dst + row * 144 + seg * 16, src);
        }
    };
    auto loadB = [&](int kc, int buf) {
        uint32_t dst = sbase + GA_B_OFF + buf * GA_B_BUF;
#pragma unroll
        for (int q = 0; q < 4; q++) {
            int i2 = tid + q * 256;
            int row = i2 >> 3, seg = i2 & 7;
            const char* src = (const char*)(g_wf16 +
                (size_t)(bn + row) * DMODEL + kc * 64 + seg * 8);
            CP_ASYNC16(dst + row * 144 + seg * 16, src);
        }
    };

    float acc[2][4][4];
#pragma unroll
    for (int mt = 0; mt < 2; mt++)
#pragma unroll
        for (int nt = 0; nt < 4; nt++)
#pragma unroll
            for (int i = 0; i < 4; i++) acc[mt][nt][i] = 0.f;

    const uint32_t aBase0 = sbase +
        (uint32_t)((wm * 32 + (lane & 15)) * 144 + (lane >> 4) * 16);
    const uint32_t bBase0 = sbase + GA_B_OFF +
        (uint32_t)((wn * 32 + (lane & 7)) * 144 + ((lane >> 3) & 1) * 16);

    loadA(0, 0); loadB(0, 0); CP_COMMIT();
#pragma unroll 1
    for (int kc = 0; kc < 8; kc++) {
        if (kc < 7) {
            loadA(kc + 1, (kc + 1) & 1);
            loadB(kc + 1, (kc + 1) & 1);
            CP_COMMIT();
            CP_WAIT(1);
        } else {
            CP_WAIT(0);
        }
        __syncthreads();
        const uint32_t aB = aBase0 + (kc & 1) * GA_A_BUF;
        const uint32_t bC = bBase0 + (kc & 1) * GA_B_BUF;
#pragma unroll
        for (int k16 = 0; k16 < 4; k16++) {
            const uint32_t koff = k16 * 32;
            uint32_t ah[2][4], bb[4][2];
#pragma unroll
            for (int mt = 0; mt < 2; mt++)
                LDSM_X4(ah[mt][0], ah[mt][1], ah[mt][2], ah[mt][3],
                        aB + mt * 2304 + koff);
#pragma unroll
            for (int nt = 0; nt < 4; nt++)
                LDSM_X2(bb[nt][0], bb[nt][1], bC + nt * 1152 + koff);
#pragma unroll
            for (int mt = 0; mt < 2; mt++)
#pragma unroll
                for (int nt = 0; nt < 4; nt++)
                    MMA16816F16(acc[mt][nt], ah[mt], bb[nt]);
        }
        __syncthreads();
    }

#pragma unroll
    for (int mt = 0; mt < 2; mt++) {
#pragma unroll
        for (int h = 0; h < 2; h++) {
            int m = bm + wm * 32 + mt * 16 + (lane >> 2) + 8 * h;
#pragma unroll
            for (int nt = 0; nt < 4; nt++) {
                int n = bn + wn * 32 + nt * 8 + (lane & 3) * 2;
                float v0 = gelu_exact(acc[mt][nt][2 * h]);
                float v1 = gelu_exact(acc[mt][nt][2 * h + 1]);
                *(float2*)&g_acts[(size_t)m * FF + n] = make_float2(v0, v1);
            }
        }
    }
}

// ======================= fused prep: prep_f + range + zero =================
// blocks [0, FF]: per-f LN1 constants (block FF = scalars)
// blocks (FF, FF+FF]: per-f a-range
// blocks beyond: zero aggT / c0
__global__ void __launch_bounds__(256) prep_misc(const float* __restrict__ phi_b1,
                                                 const float* __restrict__ phi_w1) {
    int bid = blockIdx.x;
    int tid = threadIdx.x, lane = tid & 31, wid = tid >> 5;

    if (bid <= FF) {
        float w = phi_w1[tid * (DN + 1) + DN];
        if (bid == FF) {
            float s0 = w, s1 = w * w;
#pragma unroll
            for (int o = 16; o; o >>= 1) {
                s0 += __shfl_xor_sync(~0u, s0, o);
                s1 += __shfl_xor_sync(~0u, s1, o);
            }
            __shared__ float r0[8], r1[8];
            if (lane == 0) { r0[wid] = s0; r1[wid] = s1; }
            __syncthreads();
            if (tid == 0) {
                float t0 = 0.f, t1 = 0.f;
                for (int i = 0; i < 8; i++) { t0 += r0[i]; t1 += r1[i]; }
                g_wscal[0] = t0 * (1.f / DH);
                g_wscal[1] = t1 * (1.f / DH);
            }
            return;
        }
        int f = bid;
        float p = g_nvproj[f * DH + tid] + phi_b1[tid];
        float s0 = p, s1 = p * p, s2 = p * w;
#pragma unroll
        for (int o = 16; o; o >>= 1) {
            s0 += __shfl_xor_sync(~0u, s0, o);
            s1 += __shfl_xor_sync(~0u, s1, o);
            s2 += __shfl_xor_sync(~0u, s2, o);
        }
        __shared__ float r0[8], r1[8], r2[8];
        if (lane == 0) { r0[wid] = s0; r1[wid] = s1; r2[wid] = s2; }
        __syncthreads();
        if (tid == 0) {
            float t0 = 0.f, t1 = 0.f, t2 = 0.f;
            for (int i = 0; i < 8; i++) { t0 += r0[i]; t1 += r1[i]; t2 += r2[i]; }
            g_fc[f] = make_float4(t0 * (1.f / DH), t1 * (1.f / DH),
                                  t2 * (1.f / DH), 0.f);
        }
        return;
    }

    int b2 = bid - FF - 1;
    if (b2 < FF) {
        int f = b2;
        float v0 = g_acts[(size_t)tid * FF + f];
        float v1 = g_acts[(size_t)(tid + 256) * FF + f];
        float mn = fminf(v0, v1), mx = fmaxf(v0, v1);
#pragma unroll
        for (int o = 16; o; o >>= 1) {
            mn = fminf(mn, __shfl_xor_sync(~0u, mn, o));
            mx = fmaxf(mx, __shfl_xor_sync(~0u, mx, o));
        }
        __shared__ float smn[8], smx[8];
        if (lane == 0) { smn[wid] = mn; smx[wid] = mx; }
        __syncthreads();
        if (tid == 0) {
            float a = smn[0], b = smx[0];
#pragma unroll
            for (int i = 1; i < 8; i++) { a = fminf(a, smn[i]); b = fmaxf(b, smx[i]); }
            float c = 0.5f * (b + a), h = 0.5f * (b - a) + 1e-6f;
            g_cf[f] = c; g_hf[f] = h; g_ihf[f] = 1.0f / h;
        }
    } else {
        int i = (b2 - FF) * 256 + tid;
        if (i < DH * TOK) g_aggT[i] = 0.f;
        if (i < DH) g_c0[i] = 0.f;
    }
}

// ======================= node evaluation =====================
constexpr int CONST_B1   = 0;
constexpr int CONST_WACT = 256;
constexpr int CONST_L1G  = 512;
constexpr int CONST_L1B  = 768;
constexpr int CONST_B2   = 1024;
constexpr int CONST_L2G  = 1280;
constexpr int CONST_L2B  = 1536;
constexpr int SR1_OFF    = 1792;
constexpr int SR2_OFF    = 2304;
constexpr int SMU_OFF    = 2816;
constexpr int SIS_OFF    = 2944;
constexpr int A_OFF      = 12288;
constexpr int A_BUF      = 18432;
constexpr int B_OFF      = A_OFF + 2 * A_BUF;
constexpr int B_CHUNK    = 36864;
constexpr int NE_SMEM    = B_OFF + 4 * B_CHUNK;   // 196608

__global__ void __launch_bounds__(256, 1) node_eval(
    const float* __restrict__ phi_b1, const float* __restrict__ phi_w1,
    const float* __restrict__ ln1g, const float* __restrict__ ln1b,
    const float* __restrict__ b2, const float* __restrict__ ln2g,
    const float* __restrict__ ln2b)
{
    extern __shared__ char smem[];
    float* sF = (float*)smem;
    const uint32_t sbase = smem_to_u32(smem);

    const int tid = threadIdx.x, lane = tid & 31, wid = tid >> 5;
    const int fg = blockIdx.x & 15;
    const int s  = blockIdx.x >> 4;
    const int fbase = fg * 128;
    const float xs = cospif((float)(2 * s + 1) / (2.0f * NNODES));

    {
        uint32_t dst = sbase + B_OFF + tid * 16;
        const char* src = (const char*)g_w2f16 + tid * 16;
#pragma unroll
        for (int i = 0; i < 36; i++)
            CP_ASYNC16(dst + i * 4096, src + i * 4096);
        CP_COMMIT();
    }

    sF[CONST_B1 + tid]   = phi_b1[tid];
    sF[CONST_WACT + tid] = phi_w1[tid * (DN + 1) + DN];
    sF[CONST_L1G + tid]  = ln1g[tid];
    sF[CONST_L1B + tid]  = ln1b[tid];
    sF[CONST_B2 + tid]   = b2[tid];
    sF[CONST_L2G + tid]  = ln2g[tid];
    sF[CONST_L2B + tid]  = ln2b[tid];
    __syncthreads();

    const int g = wid >> 2, wn = wid & 3;
    const int wg_tid = tid & 127;

    const int row = wg_tid >> 1;
    const int khalf = wg_tid & 1;
    const int f = fbase + g * 64 + row;
    const float a = g_cf[f] + g_hf[f] * xs;
    const float4 fc = g_fc[f];
    const float mean = fc.x + a * g_wscal[0];
    const float e2 = fc.y + 2.f * a * fc.z + a * a * g_wscal[1];
    const float istd = rsqrtf(e2 - mean * mean + LN_EPS);
    const float nmi = -mean * istd;

    char* const aDst0 = smem + A_OFF + g * 9216 + row * 144 + khalf * 64;
    const float* const nvRow = g_nvproj + (size_t)f * DH + khalf * 32;

    auto produce = [&](int kc, int buf) {
        const float* nvp = nvRow + kc * 64;
        char* aDst = aDst0 + buf * A_BUF;
#pragma unroll 2
        for (int u = 0; u < 8; u++) {
            float4 pv = *(const float4*)(nvp + u * 4);
            float p4[4] = {pv.x, pv.y, pv.z, pv.w};
            float gv[4];
            int kb = kc * 64 + khalf * 32 + u * 4;
#pragma unroll
            for (int e = 0; e < 4; e++) {
                int k = kb + e;
                float val = fmaf(a, sF[CONST_WACT + k], p4[e] + sF[CONST_B1 + k]);
                float sc = fmaf(val, istd, nmi);
                float xx = fmaf(sc, sF[CONST_L1G + k], sF[CONST_L1B + k]);
                gv[e] = gelu_exact(xx);
            }
            *(uint2*)(aDst + u * 8) =
                make_uint2(pack_f16(gv[0], gv[1]), pack_f16(gv[2], gv[3]));
        }
    };

    float acc[4][8][4];
#pragma unroll
    for (int mt = 0; mt < 4; mt++)
#pragma unroll
        for (int nt = 0; nt < 8; nt++)
#pragma unroll
            for (int i = 0; i < 4; i++) acc[mt][nt][i] = 0.f;

    const uint32_t aBase0 = sbase + A_OFF + g * 9216 +
        (uint32_t)((lane & 15) * 144 + (lane >> 4) * 16);
    const uint32_t bBase = sbase + B_OFF +
        (uint32_t)((wn * 64 + (lane & 7)) * 144 + ((lane >> 3) & 1) * 16);

    auto mma_chunk = [&](int kc) {
        const uint32_t aB = aBase0 + (kc & 1) * A_BUF;
        const uint32_t bC = bBase + kc * B_CHUNK;
#pragma unroll
        for (int k16 = 0; k16 < 4; k16++) {
            const uint32_t koff = k16 * 32;
            uint32_t ah[4][4], bb[8][2];
#pragma unroll
            for (int mt = 0; mt < 4; mt++)
                LDSM_X4(ah[mt][0], ah[mt][1], ah[mt][2], ah[mt][3],
                        aB + mt * 2304 + koff);
#pragma unroll
            for (int nt = 0; nt < 8; nt++)
                LDSM_X2(bb[nt][0], bb[nt][1], bC + nt * 1152 + koff);
#pragma unroll
            for (int mt = 0; mt < 4; mt++)
#pragma unroll
                for (int nt = 0; nt < 8; nt++)
                    MMA16816F16(acc[mt][nt], ah[mt], bb[nt]);
        }
    };

    produce(0, 0);
    CP_WAIT(0);
    __syncthreads();
#pragma unroll
    for (int kc = 0; kc < 4; kc++) {
        mma_chunk(kc);
        if (kc < 3) produce(kc + 1, (kc + 1) & 1);
        __syncthreads();
    }

    float b2c[16], gc[16], bc[16];
#pragma unroll
    for (int nt = 0; nt < 8; nt++) {
        int j0 = wn * 64 + nt * 8 + (lane & 3) * 2;
        b2c[2 * nt]     = sF[CONST_B2 + j0];
        b2c[2 * nt + 1] = sF[CONST_B2 + j0 + 1];
        gc[2 * nt]      = sF[CONST_L2G + j0];
        gc[2 * nt + 1]  = sF[CONST_L2G + j0 + 1];
        bc[2 * nt]      = sF[CONST_L2B + j0];
        bc[2 * nt + 1]  = sF[CONST_L2B + j0 + 1];
    }

#pragma unroll
    for (int mt = 0; mt < 4; mt++) {
#pragma unroll
        for (int h = 0; h < 2; h++) {
            float s1 = 0.f, s2 = 0.f;
#pragma unroll
            for (int nt = 0; nt < 8; nt++) {
                float y0 = acc[mt][nt][2 * h]     + b2c[2 * nt];
                float y1 = acc[mt][nt][2 * h + 1] + b2c[2 * nt + 1];
                acc[mt][nt][2 * h]     = y0;
                acc[mt][nt][2 * h + 1] = y1;
                s1 += y0 + y1;
                s2 += y0 * y0 + y1 * y1;
            }
            s1 += __shfl_xor_sync(~0u, s1, 1);
            s1 += __shfl_xor_sync(~0u, s1, 2);
            s2 += __shfl_xor_sync(~0u, s2, 1);
            s2 += __shfl_xor_sync(~0u, s2, 2);
            if ((lane & 3) == 0) {
                int r = mt * 16 + (lane >> 2) + 8 * h;
                sF[SR1_OFF + g * 256 + r * 4 + wn] = s1;
                sF[SR2_OFF + g * 256 + r * 4 + wn] = s2;
            }
        }
    }
    __syncthreads();
    if (wg_tid < 64) {
        int base = SR1_OFF + g * 256 + wg_tid * 4;
        float s1 = sF[base] + sF[base + 1] + sF[base + 2] + sF[base + 3];
        int base2 = SR2_OFF + g * 256 + wg_tid * 4;
        float s2 = sF[base2] + sF[base2 + 1] + sF[base2 + 2] + sF[base2 + 3];
        float mu = s1 * (1.f / DH);
        float vr = s2 * (1.f / DH) - mu * mu;
        sF[SMU_OFF + g * 64 + wg_tid] = mu;
        sF[SIS_OFF + g * 64 + wg_tid] = rsqrtf(vr + LN_EPS);
    }
    __syncthreads();

#pragma unroll
    for (int mt = 0; mt < 4; mt++) {
#pragma unroll
        for (int h = 0; h < 2; h++) {
            int r = mt * 16 + (lane >> 2) + 8 * h;
            float mu = sF[SMU_OFF + g * 64 + r];
            float is = sF[SIS_OFF + g * 64 + r];
            int fr = fbase + g * 64 + r;
            float* zp = g_znodes + ((size_t)fr * NNODES + s) * DH;
#pragma unroll
            for (int nt = 0; nt < 8; nt++) {
                float z0 = (acc[mt][nt][2 * h]     - mu) * is * gc[2 * nt]     + bc[2 * nt];
                float z1 = (acc[mt][nt][2 * h + 1] - mu) * is * gc[2 * nt + 1] + bc[2 * nt + 1];
                *(float2*)(zp + wn * 64 + nt * 8 + (lane & 3) * 2) =
                    make_float2(z0, z1);
            }
        }
    }
}

// ======================= Chebyshev transform (symmetry-folded) =============
// cos(j*pi*(2*(31-s)+1)/64) = (-1)^j cos(j*pi*(2s+1)/64) -> fold z into
// even/odd halves; inner product over 16 terms instead of 32.
__global__ void __launch_bounds__(256) cheb_transform() {
    __shared__ float cosm[NNODES * (NNODES / 2)];   // [j][s<16]
    int tid = threadIdx.x;
#pragma unroll
    for (int i = 0; i < 2; i++) {
        int e = tid + i * 256;
        int j = e >> 4, sx = e & 15;
        cosm[e] = cospif((float)(j * (2 * sx + 1)) / (2.0f * NNODES));
    }
    __syncthreads();

    int f = blockIdx.x;
    const float* zb = g_znodes + (size_t)f * NNODES * DH + tid;
    float ze[NNODES / 2], zo[NNODES / 2];
#pragma unroll
    for (int sx = 0; sx < NNODES / 2; sx++) {
        float zl = zb[sx * DH];
        float zh = zb[(NNODES - 1 - sx) * DH];
        ze[sx] = zl + zh;
        zo[sx] = zl - zh;
    }

    float c0 = 0.f;
#pragma unroll
    for (int sx = 0; sx < NNODES / 2; sx++) c0 += ze[sx];
    c0 *= (1.0f / NNODES);
    atomicAdd(&g_c0[tid], c0);

    float cj[NNODES];
    cj[0] = 0.f;   // j=0 handled exactly via g_c0
#pragma unroll
    for (int j = 1; j < NNODES; j++) {
        const float* zz = (j & 1) ? zo : ze;
        float c = 0.f;
#pragma unroll
        for (int sx = 0; sx < NNODES / 2; sx++)
            c = fmaf(zz[sx], cosm[j * (NNODES / 2) + sx], c);
        cj[j] = c * (2.0f / NNODES);
    }
    uint32_t u[NNODES / 2];
#pragma unroll
    for (int i = 0; i < NNODES / 2; i++)
        u[i] = pack_f16(cj[2 * i], cj[2 * i + 1]);
    uint4* dst = (uint4*)(g_cT + (size_t)tid * (FF * NNODES) + f * NNODES);
#pragma unroll
    for (int i = 0; i < 4; i++)
        dst[i] = make_uint4(u[4 * i], u[4 * i + 1], u[4 * i + 2], u[4 * i + 3]);
}

// ======================= final GEMM: aggT[256,512] = C_T @ T^T ==========
// T computed ON THE FLY from g_acts (Chebyshev recurrence).
constexpr int FG_A0 = 0;
constexpr int FG_A1 = 18432;
constexpr int FG_B0 = 36864;
constexpr int FG_B1 = 73728;
constexpr int FG_SMEM = 110592;
constexpr int KTOT = FF * NNODES;

__global__ void __launch_bounds__(256, 1) gemm_final() {
    extern __shared__ char smem[];
    const uint32_t sbase = smem_to_u32(smem);
    const int tid = threadIdx.x, lane = tid & 31, wid = tid >> 5;
    const int mtile = blockIdx.x & 1;
    const int ntile = (blockIdx.x >> 1) & 1;
    const int ks = blockIdx.x >> 2;
    const int k0 = ks * 2048;
    const int g = wid >> 2, wn = wid & 3;

    auto loadA = [&](int kc, int buf) {
        uint32_t dst = sbase + (buf ? FG_A1 : FG_A0);
#pragma unroll
        for (int q = 0; q < 4; q++) {
            int i2 = tid + q * 256;
            int row = i2 >> 3, seg = i2 & 7;
            const char* src = (const char*)(g_cT +
                (size_t)(mtile * 128 + row) * KTOT + k0 + kc * 64 + seg * 8);
            CP_ASYNC16(dst + row * 144 + seg * 16, src);
        }
    };

    auto produceB = [&](int kc, int buf) {
        char* dstBase = smem + (buf ? FG_B1 : FG_B0);
        const int fbase2 = ks * 64 + kc * 2;
#pragma unroll
        for (int q = 0; q < 2; q++) {
            int p = tid + q * 256;
            int r = p >> 1, fh = p & 1;
            int f = fbase2 + fh;
            float a = g_acts[(size_t)(ntile * 256 + r) * FF + f];
            float x = (a - g_cf[f]) * g_ihf[f];
            x = fminf(1.f, fmaxf(-1.f, x));
            float T[NNODES];
            T[0] = 1.f; T[1] = x;
            float x2 = 2.f * x;
#pragma unroll
            for (int j = 2; j < NNODES; j++) T[j] = fmaf(x2, T[j - 1], -T[j - 2]);
            uint32_t u[NNODES / 2];
#pragma unroll
            for (int i = 0; i < NNODES / 2; i++)
                u[i] = pack_f16(T[2 * i], T[2 * i + 1]);
            char* d = dstBase + r * 144 + fh * 64;
#pragma unroll
            for (int i = 0; i < 4; i++)
                *(uint4*)(d + i * 16) =
                    make_uint4(u[4 * i], u[4 * i + 1], u[4 * i + 2], u[4 * i + 3]);
        }
    };

    float acc[4][8][4];
#pragma unroll
    for (int mt = 0; mt < 4; mt++)
#pragma unroll
        for (int nt = 0; nt < 8; nt++)
#pragma unroll
            for (int i = 0; i < 4; i++) acc[mt][nt][i] = 0.f;

    const uint32_t aBase0 = sbase + FG_A0 +
        (uint32_t)((g * 64 + (lane & 15)) * 144 + (lane >> 4) * 16);
    const uint32_t bBase0 = sbase + FG_B0 +
        (uint32_t)((wn * 64 + (lane & 7)) * 144 + ((lane >> 3) & 1) * 16);

    auto mma_chunk = [&](int kc) {
        const uint32_t aB = aBase0 + (kc & 1) * (FG_A1 - FG_A0);
        const uint32_t bC = bBase0 + (kc & 1) * (FG_B1 - FG_B0);
#pragma unroll
        for (int k16 = 0; k16 < 4; k16++) {
            const uint32_t koff = k16 * 32;
            uint32_t ah[4][4], bb[8][2];
#pragma unroll
            for (int mt = 0; mt < 4; mt++)
                LDSM_X4(ah[mt][0], ah[mt][1], ah[mt][2], ah[mt][3],
                        aB + mt * 2304 + koff);
#pragma unroll
            for (int nt = 0; nt < 8; nt++)
                LDSM_X2(bb[nt][0], bb[nt][1], bC + nt * 1152 + koff);
#pragma unroll
            for (int mt = 0; mt < 4; mt++)
#pragma unroll
                for (int nt = 0; nt < 8; nt++)
                    MMA16816F16(acc[mt][nt], ah[mt], bb[nt]);
        }
    };

    loadA(0, 0); CP_COMMIT();
    produceB(0, 0);
    CP_WAIT(0);
    __syncthreads();
#pragma unroll 1
    for (int kc = 0; kc < 32; kc++) {
        if (kc < 31) { loadA(kc + 1, (kc + 1) & 1); CP_COMMIT(); }
        mma_chunk(kc);
        if (kc < 31) {
            produceB(kc + 1, (kc + 1) & 1);
            CP_WAIT(0);
        }
        __syncthreads();
    }

#pragma unroll
    for (int mt = 0; mt < 4; mt++) {
#pragma unroll
        for (int h = 0; h < 2; h++) {
            int row = mtile * 128 + g * 64 + mt * 16 + (lane >> 2) + 8 * h;
#pragma unroll
            for (int nt = 0; nt < 8; nt++) {
#pragma unroll
                for (int e = 0; e < 2; e++) {
                    int col = ntile * 256 + wn * 64 + nt * 8 + (lane & 3) * 2 + e;
                    atomicAdd(&g_aggT[row * TOK + col], acc[mt][nt][2 * h + e]);
                }
            }
        }
    }
}

// ---------------- final LN over agg (transposed layout + c0) ------------
__global__ void __launch_bounds__(256) ln256_kernel(
    const float* __restrict__ g, const float* __restrict__ b)
{
    int t = blockIdx.x;
    int tid = threadIdx.x;
    int lane = tid & 31, wid = tid >> 5;
    float v = g_aggT[(size_t)tid * TOK + t] + g_c0[tid];
    float s1 = v, s2 = v * v;
#pragma unroll
    for (int o = 16; o; o >>= 1) {
        s1 += __shfl_xor_sync(~0u, s1, o);
        s2 += __shfl_xor_sync(~0u, s2, o);
    }
    __shared__ float r1[8], r2[8];
    if (lane == 0) { r1[wid] = s1; r2[wid] = s2; }
    __syncthreads();
    float t1 = 0.f, t2 = 0.f;
#pragma unroll
    for (int w = 0; w < 8; w++) { t1 += r1[w]; t2 += r2[w]; }
    float mean = t1 * (1.f / DH);
    float var = t2 * (1.f / DH) - mean * mean;
    float istd = rsqrtf(var + LN_EPS);
    g_r[t * DH + tid] = (v - mean) * istd * g[tid] + b[tid];
}

// ---------------- launch ----------------
extern "C" void kernel_launch(void* const* d_in, const int* in_sizes, int n_in,
                              void* d_out, int out_size)
{
    const float* x      = (const float*)d_in[0];
    const float* nv     = (const float*)d_in[1];
    const float* W_in   = (const float*)d_in[2];
    const float* phi_w1 = (const float*)d_in[3];
    const float* phi_b1 = (const float*)d_in[4];
    const float* ln1g   = (const float*)d_in[5];
    const float* ln1b   = (const float*)d_in[6];
    const float* phi_w2 = (const float*)d_in[7];
    const float* phi_b2 = (const float*)d_in[8];
    const float* ln2g   = (const float*)d_in[9];
    const float* ln2b   = (const float*)d_in[10];
    const float* rln_g  = (const float*)d_in[11];
    const float* rln_b  = (const float*)d_in[12];
    const float* rho_w1 = (const float*)d_in[13];
    const float* rho_b1 = (const float*)d_in[14];
    const float* rho_w2 = (const float*)d_in[15];
    const float* rho_b2 = (const float*)d_in[16];
    float* out = (float*)d_out;

    const int conv_total = TOK * DMODEL + FF * DMODEL + DH * DH;
    prep_conv<<<(conv_total + 255) / 256, 256>>>(x, W_in, phi_w2);      // 1

    cudaFuncSetAttribute(gemm_acts_f16,
                         cudaFuncAttributeMaxDynamicSharedMemorySize, GA_SMEM);
    gemm_acts_f16<<<dim3(8, 16), 256, GA_SMEM>>>();                     // 2

    gemm_nvproj<<<dim3(FF / 64, DH / 128), 256>>>(nv, phi_w1);          // 3

    // prep_f (FF+1 blocks) + range (FF blocks) + zero (512 blocks)
    prep_misc<<<FF + 1 + FF + 512, 256>>>(phi_b1, phi_w1);              // 4

    cudaFuncSetAttribute(node_eval, cudaFuncAttributeMaxDynamicSharedMemorySize,
                         NE_SMEM);
    node_eval<<<16 * NNODES, 256, NE_SMEM>>>(phi_b1, phi_w1, ln1g, ln1b,
                                             phi_b2, ln2g, ln2b);       // 5

    cheb_transform<<<FF, 256>>>();                                      // 6

    cudaFuncSetAttribute(gemm_final, cudaFuncAttributeMaxDynamicSharedMemorySize,
                         FG_SMEM);
    gemm_final<<<128, 256, FG_SMEM>>>();                                // 7

    ln256_kernel<<<TOK, 256>>>(rln_g, rln_b);                           // 8
    gemm_rho1<<<dim3(TOK / 64, DH2 / 128), 256>>>(rho_w1, rho_b1);      // 9
    gemm_rho2<<<dim3(TOK / 64, DMODEL / 128), 256>>>(rho_w2, rho_b2, out); // 10

    (void)in_sizes; (void)n_in; (void)out_size;
}

// round 16
// speedup vs baseline: 2.3959x; 1.1107x over previous
#include <cuda_runtime.h>
#include <cuda_fp16.h>
#include <math.h>
#include <stdint.h>

#define TOK 512
#define DMODEL 512
#define FF 2048
#define DN 128
#define DH 256
#define DH2 512
#define LN_EPS 1e-5f
#define NNODES 32   // coefficient slots (layout)
#define NQ 24       // quadrature nodes actually evaluated

// ---------------- scratch (no allocation allowed) ----------------
__device__ float g_acts[TOK * FF];
__device__ float g_nvproj[FF * DH];
__device__ float g_aggT[DH * TOK];          // [k][t]
__device__ float g_c0[DH];
__device__ float g_r[TOK * DH];
__device__ float g_r2[TOK * DH2];
__device__ __align__(16) __half g_w2f16[4][256 * 72];
__device__ __align__(16) __half g_xf16[TOK * DMODEL];
__device__ __align__(16) __half g_wf16[FF * DMODEL];
__device__ float4 g_fc[FF];                 // per-f LN1 constants
__device__ float g_wscal[2];
__device__ float g_cf[FF];                  // a-range center
__device__ float g_hf[FF];                  // a-range half width
__device__ float g_ihf[FF];                 // 1 / half width
__device__ __align__(16) float g_znodes[FF * NQ * DH];
__device__ __align__(16) __half g_cT[DH * FF * NNODES];    // [k][f*32+j]

__device__ __forceinline__ float gelu_exact(float x) {
    return 0.5f * x * (1.0f + erff(x * 0.70710678118654752440f));
}

__device__ __forceinline__ uint32_t smem_to_u32(const void* p) {
    uint32_t a;
    asm("{ .reg .u64 t; cvta.to.shared.u64 t, %1; cvt.u32.u64 %0, t; }"
        : "=r"(a) : "l"(p));
    return a;
}

__device__ __forceinline__ uint32_t pack_f16(float e0, float e1) {
    uint32_t r;  // e0 -> low half
    asm("cvt.rn.f16x2.f32 %0, %1, %2;" : "=r"(r) : "f"(e1), "f"(e0));
    return r;
}

#define LDSM_X4(r0, r1, r2, r3, addr) \
    asm volatile("ldmatrix.sync.aligned.m8n8.x4.shared.b16 {%0,%1,%2,%3}, [%4];" \
        : "=r"(r0), "=r"(r1), "=r"(r2), "=r"(r3) : "r"(addr))
#define LDSM_X2(r0, r1, addr) \
    asm volatile("ldmatrix.sync.aligned.m8n8.x2.shared.b16 {%0,%1}, [%2];" \
        : "=r"(r0), "=r"(r1) : "r"(addr))
#define MMA16816F16(d, a, b) \
    asm volatile("mma.sync.aligned.m16n8k16.row.col.f32.f16.f16.f32 " \
        "{%0,%1,%2,%3}, {%4,%5,%6,%7}, {%8,%9}, {%0,%1,%2,%3};" \
        : "+f"((d)[0]), "+f"((d)[1]), "+f"((d)[2]), "+f"((d)[3]) \
        : "r"((a)[0]), "r"((a)[1]), "r"((a)[2]), "r"((a)[3]), \
          "r"((b)[0]), "r"((b)[1]))
#define CP_ASYNC16(dst, src) \
    asm volatile("cp.async.cg.shared.global [%0], [%1], 16;" \
        :: "r"(dst), "l"(src) : "memory")
#define CP_COMMIT() asm volatile("cp.async.commit_group;" ::: "memory")
#define CP_WAIT(n)  asm volatile("cp.async.wait_group %0;" :: "n"(n) : "memory")

// ======================= generic SIMT GEMM (small stages) ==================
template <bool GELU, bool BIAS>
__device__ __forceinline__ void gemm_tn_body(
    const float* __restrict__ A, int lda,
    const float* __restrict__ B, int ldb,
    const float* __restrict__ bias,
    float* __restrict__ C, int ldc, int K)
{
    constexpr int BM = 64, BN = 128, BK = 32;
    __shared__ float sA[BK][BM + 2];
    __shared__ float sB[BK][BN + 2];
    int tid = threadIdx.x;
    int lane = tid & 31, wid = tid >> 5;
    int bm = blockIdx.x * BM, bn = blockIdx.y * BN;

    float acc[8][4];
#pragma unroll
    for (int i = 0; i < 8; i++)
#pragma unroll
        for (int u = 0; u < 4; u++) acc[i][u] = 0.f;

    for (int k0 = 0; k0 < K; k0 += BK) {
#pragma unroll
        for (int r = 0; r < 8; r++) {
            int m = wid + 8 * r;
            sA[lane][m] = A[(size_t)(bm + m) * lda + k0 + lane];
        }
#pragma unroll
        for (int r = 0; r < 16; r++) {
            int n = wid + 8 * r;
            sB[lane][n] = B[(size_t)(bn + n) * ldb + k0 + lane];
        }
        __syncthreads();
#pragma unroll
        for (int kk = 0; kk < BK; kk++) {
            float a[8], b[4];
#pragma unroll
            for (int i = 0; i < 8; i++) a[i] = sA[kk][wid * 8 + i];
#pragma unroll
            for (int u = 0; u < 4; u++) b[u] = sB[kk][lane + 32 * u];
#pragma unroll
            for (int i = 0; i < 8; i++)
#pragma unroll
                for (int u = 0; u < 4; u++) acc[i][u] += a[i] * b[u];
        }
        __syncthreads();
    }
#pragma unroll
    for (int i = 0; i < 8; i++) {
        int m = bm + wid * 8 + i;
#pragma unroll
        for (int u = 0; u < 4; u++) {
            int n = bn + lane + 32 * u;
            float v = acc[i][u];
            if (BIAS) v += bias[n];
            if (GELU) v = gelu_exact(v);
            C[(size_t)m * ldc + n] = v;
        }
    }
}

__global__ void __launch_bounds__(256) gemm_nvproj(const float* __restrict__ nv,
                                                   const float* __restrict__ phi_w1)
{   gemm_tn_body<false, false>(nv, DN, phi_w1, DN + 1, nullptr, g_nvproj, DH, DN); }

__global__ void __launch_bounds__(256) gemm_rho1(const float* __restrict__ rho_w1,
                                                 const float* __restrict__ rho_b1)
{   gemm_tn_body<true, true>(g_r, DH, rho_w1, DH, rho_b1, g_r2, DH2, DH); }

__global__ void __launch_bounds__(256) gemm_rho2(const float* __restrict__ rho_w2,
                                                 const float* __restrict__ rho_b2,
                                                 float* __restrict__ out)
{   gemm_tn_body<false, true>(g_r2, DH2, rho_w2, DH2, rho_b2, out, DMODEL, DH2); }

// ======================= fused convert prep =======================
__global__ void __launch_bounds__(256) prep_conv(const float* __restrict__ x,
                                                 const float* __restrict__ W_in,
                                                 const float* __restrict__ w2) {
    int idx = blockIdx.x * 256 + threadIdx.x;
    if (idx < TOK * DMODEL) g_xf16[idx] = __float2half(x[idx]);
    int i2 = idx - TOK * DMODEL;
    if (i2 >= 0 && i2 < FF * DMODEL) g_wf16[i2] = __float2half(W_in[i2]);
    int i3 = i2 - FF * DMODEL;
    if (i3 >= 0 && i3 < DH * DH) {
        int j = i3 >> 8, k = i3 & 255;
        int kc = k >> 6, kin = k & 63;
        g_w2f16[kc][j * 72 + kin] = __float2half(w2[i3]);
    }
}

// ======================= fp16 tensor acts GEMM =====================
constexpr int GA_A_BUF = 9216;    // 64 x 144
constexpr int GA_B_OFF = 18432;
constexpr int GA_B_BUF = 18432;   // 128 x 144
constexpr int GA_SMEM  = 55296;

__global__ void __launch_bounds__(256) gemm_acts_f16() {
    extern __shared__ char smem[];
    const uint32_t sbase = smem_to_u32(smem);
    const int tid = threadIdx.x, lane = tid & 31, wid = tid >> 5;
    const int bm = blockIdx.x * 64, bn = blockIdx.y * 128;
    const int wm = wid & 1, wn = wid >> 1;

    auto loadA = [&](int kc, int buf) {
        uint32_t dst = sbase + buf * GA_A_BUF;
#pragma unroll
        for (int q = 0; q < 2; q++) {
            int i2 = tid + q * 256;
            int row = i2 >> 3, seg = i2 & 7;
            const char* src = (const char*)(g_xf16 +
                (size_t)(bm + row) * DMODEL + kc * 64 + seg * 8);
            CP_ASYNC16(dst + row * 144 + seg * 16, src);
        }
    };
    auto loadB = [&](int kc, int buf) {
        uint32_t dst = sbase + GA_B_OFF + buf * GA_B_BUF;
#pragma unroll
        for (int q = 0; q < 4; q++) {
            int i2 = tid + q * 256;
            int row = i2 >> 3, seg = i2 & 7;
            const char* src = (const char*)(g_wf16 +
                (size_t)(bn + row) * DMODEL + kc * 64 + seg * 8);
            CP_ASYNC16(dst + row * 144 + seg * 16, src);
        }
    };

    float acc[2][4][4];
#pragma unroll
    for (int mt = 0; mt < 2; mt++)
#pragma unroll
        for (int nt = 0; nt < 4; nt++)
#pragma unroll
            for (int i = 0; i < 4; i++) acc[mt][nt][i] = 0.f;

    const uint32_t aBase0 = sbase +
        (uint32_t)((wm * 32 + (lane & 15)) * 144 + (lane >> 4) * 16);
    const uint32_t bBase0 = sbase + GA_B_OFF +
        (uint32_t)((wn * 32 + (lane & 7)) * 144 + ((lane >> 3) & 1) * 16);

    loadA(0, 0); loadB(0, 0); CP_COMMIT();
#pragma unroll 1
    for (int kc = 0; kc < 8; kc++) {
        if (kc < 7) {
            loadA(kc + 1, (kc + 1) & 1);
            loadB(kc + 1, (kc + 1) & 1);
            CP_COMMIT();
            CP_WAIT(1);
        } else {
            CP_WAIT(0);
        }
        __syncthreads();
        const uint32_t aB = aBase0 + (kc & 1) * GA_A_BUF;
        const uint32_t bC = bBase0 + (kc & 1) * GA_B_BUF;
#pragma unroll
        for (int k16 = 0; k16 < 4; k16++) {
            const uint32_t koff = k16 * 32;
            uint32_t ah[2][4], bb[4][2];
#pragma unroll
            for (int mt = 0; mt < 2; mt++)
                LDSM_X4(ah[mt][0], ah[mt][1], ah[mt][2], ah[mt][3],
                        aB + mt * 2304 + koff);
#pragma unroll
            for (int nt = 0; nt < 4; nt++)
                LDSM_X2(bb[nt][0], bb[nt][1], bC + nt * 1152 + koff);
#pragma unroll
            for (int mt = 0; mt < 2; mt++)
#pragma unroll
                for (int nt = 0; nt < 4; nt++)
                    MMA16816F16(acc[mt][nt], ah[mt], bb[nt]);
        }
        __syncthreads();
    }

#pragma unroll
    for (int mt = 0; mt < 2; mt++) {
#pragma unroll
        for (int h = 0; h < 2; h++) {
            int m = bm + wm * 32 + mt * 16 + (lane >> 2) + 8 * h;
#pragma unroll
            for (int nt = 0; nt < 4; nt++) {
                int n = bn + wn * 32 + nt * 8 + (lane & 3) * 2;
                float v0 = gelu_exact(acc[mt][nt][2 * h]);
                float v1 = gelu_exact(acc[mt][nt][2 * h + 1]);
                *(float2*)&g_acts[(size_t)m * FF + n] = make_float2(v0, v1);
            }
        }
    }
}

// ======================= fused prep: prep_f + range + zero =================
// blocks [0, FF]: per-f LN1 constants (block FF = scalars)
// blocks (FF, FF+64]: coalesced a-range (32 f per block)
// blocks beyond: zero aggT / c0
__global__ void __launch_bounds__(256) prep_misc(const float* __restrict__ phi_b1,
                                                 const float* __restrict__ phi_w1) {
    int bid = blockIdx.x;
    int tid = threadIdx.x, lane = tid & 31, wid = tid >> 5;

    if (bid <= FF) {
        float w = phi_w1[tid * (DN + 1) + DN];
        if (bid == FF) {
            float s0 = w, s1 = w * w;
#pragma unroll
            for (int o = 16; o; o >>= 1) {
                s0 += __shfl_xor_sync(~0u, s0, o);
                s1 += __shfl_xor_sync(~0u, s1, o);
            }
            __shared__ float r0[8], r1[8];
            if (lane == 0) { r0[wid] = s0; r1[wid] = s1; }
            __syncthreads();
            if (tid == 0) {
                float t0 = 0.f, t1 = 0.f;
                for (int i = 0; i < 8; i++) { t0 += r0[i]; t1 += r1[i]; }
                g_wscal[0] = t0 * (1.f / DH);
                g_wscal[1] = t1 * (1.f / DH);
            }
            return;
        }
        int f = bid;
        float p = g_nvproj[f * DH + tid] + phi_b1[tid];
        float s0 = p, s1 = p * p, s2 = p * w;
#pragma unroll
        for (int o = 16; o; o >>= 1) {
            s0 += __shfl_xor_sync(~0u, s0, o);
            s1 += __shfl_xor_sync(~0u, s1, o);
            s2 += __shfl_xor_sync(~0u, s2, o);
        }
        __shared__ float r0[8], r1[8], r2[8];
        if (lane == 0) { r0[wid] = s0; r1[wid] = s1; r2[wid] = s2; }
        __syncthreads();
        if (tid == 0) {
            float t0 = 0.f, t1 = 0.f, t2 = 0.f;
            for (int i = 0; i < 8; i++) { t0 += r0[i]; t1 += r1[i]; t2 += r2[i]; }
            g_fc[f] = make_float4(t0 * (1.f / DH), t1 * (1.f / DH),
                                  t2 * (1.f / DH), 0.f);
        }
        return;
    }

    int b2 = bid - FF - 1;
    if (b2 < 64) {
        // coalesced range: this block owns f in [b2*32, b2*32+32)
        int f0 = b2 * 32;
        float mn = 3.4e38f, mx = -3.4e38f;
        const float* base = g_acts + f0 + lane;
        for (int r = wid * 64; r < wid * 64 + 64; r++) {
            float v = base[(size_t)r * FF];
            mn = fminf(mn, v); mx = fmaxf(mx, v);
        }
        __shared__ float smn[8][32], smx[8][32];
        smn[wid][lane] = mn; smx[wid][lane] = mx;
        __syncthreads();
        if (tid < 32) {
            float a = smn[0][tid], b = smx[0][tid];
#pragma unroll
            for (int i = 1; i < 8; i++) {
                a = fminf(a, smn[i][tid]);
                b = fmaxf(b, smx[i][tid]);
            }
            float c = 0.5f * (b + a), h = 0.5f * (b - a) + 1e-6f;
            int f = f0 + tid;
            g_cf[f] = c; g_hf[f] = h; g_ihf[f] = 1.0f / h;
        }
    } else {
        int i = (b2 - 64) * 256 + tid;
        if (i < DH * TOK) g_aggT[i] = 0.f;
        if (i < DH) g_c0[i] = 0.f;
    }
}

// ======================= node evaluation =====================
constexpr int CONST_B1   = 0;
constexpr int CONST_WACT = 256;
constexpr int CONST_L1G  = 512;
constexpr int CONST_L1B  = 768;
constexpr int CONST_B2   = 1024;
constexpr int CONST_L2G  = 1280;
constexpr int CONST_L2B  = 1536;
constexpr int SR1_OFF    = 1792;
constexpr int SR2_OFF    = 2304;
constexpr int SMU_OFF    = 2816;
constexpr int SIS_OFF    = 2944;
constexpr int A_OFF      = 12288;
constexpr int A_BUF      = 18432;
constexpr int B_OFF      = A_OFF + 2 * A_BUF;
constexpr int B_CHUNK    = 36864;
constexpr int NE_SMEM    = B_OFF + 4 * B_CHUNK;   // 196608

__global__ void __launch_bounds__(256, 1) node_eval(
    const float* __restrict__ phi_b1, const float* __restrict__ phi_w1,
    const float* __restrict__ ln1g, const float* __restrict__ ln1b,
    const float* __restrict__ b2, const float* __restrict__ ln2g,
    const float* __restrict__ ln2b)
{
    extern __shared__ char smem[];
    float* sF = (float*)smem;
    const uint32_t sbase = smem_to_u32(smem);

    const int tid = threadIdx.x, lane = tid & 31, wid = tid >> 5;
    const int fg = blockIdx.x & 15;
    const int s  = blockIdx.x >> 4;          // 0..NQ-1
    const int fbase = fg * 128;
    const float xs = cospif((float)(2 * s + 1) / (2.0f * NQ));

    {
        uint32_t dst = sbase + B_OFF + tid * 16;
        const char* src = (const char*)g_w2f16 + tid * 16;
#pragma unroll
        for (int i = 0; i < 36; i++)
            CP_ASYNC16(dst + i * 4096, src + i * 4096);
        CP_COMMIT();
    }

    sF[CONST_B1 + tid]   = phi_b1[tid];
    sF[CONST_WACT + tid] = phi_w1[tid * (DN + 1) + DN];
    sF[CONST_L1G + tid]  = ln1g[tid];
    sF[CONST_L1B + tid]  = ln1b[tid];
    sF[CONST_B2 + tid]   = b2[tid];
    sF[CONST_L2G + tid]  = ln2g[tid];
    sF[CONST_L2B + tid]  = ln2b[tid];
    __syncthreads();

    const int g = wid >> 2, wn = wid & 3;
    const int wg_tid = tid & 127;

    const int row = wg_tid >> 1;
    const int khalf = wg_tid & 1;
    const int f = fbase + g * 64 + row;
    const float a = g_cf[f] + g_hf[f] * xs;
    const float4 fc = g_fc[f];
    const float mean = fc.x + a * g_wscal[0];
    const float e2 = fc.y + 2.f * a * fc.z + a * a * g_wscal[1];
    const float istd = rsqrtf(e2 - mean * mean + LN_EPS);
    const float nmi = -mean * istd;

    char* const aDst0 = smem + A_OFF + g * 9216 + row * 144 + khalf * 64;
    const float* const nvRow = g_nvproj + (size_t)f * DH + khalf * 32;

    auto produce = [&](int kc, int buf) {
        const float* nvp = nvRow + kc * 64;
        char* aDst = aDst0 + buf * A_BUF;
#pragma unroll 2
        for (int u = 0; u < 8; u++) {
            float4 pv = *(const float4*)(nvp + u * 4);
            float p4[4] = {pv.x, pv.y, pv.z, pv.w};
            float gv[4];
            int kb = kc * 64 + khalf * 32 + u * 4;
#pragma unroll
            for (int e = 0; e < 4; e++) {
                int k = kb + e;
                float val = fmaf(a, sF[CONST_WACT + k], p4[e] + sF[CONST_B1 + k]);
                float sc = fmaf(val, istd, nmi);
                float xx = fmaf(sc, sF[CONST_L1G + k], sF[CONST_L1B + k]);
                gv[e] = gelu_exact(xx);
            }
            *(uint2*)(aDst + u * 8) =
                make_uint2(pack_f16(gv[0], gv[1]), pack_f16(gv[2], gv[3]));
        }
    };

    float acc[4][8][4];
#pragma unroll
    for (int mt = 0; mt < 4; mt++)
#pragma unroll
        for (int nt = 0; nt < 8; nt++)
#pragma unroll
            for (int i = 0; i < 4; i++) acc[mt][nt][i] = 0.f;

    const uint32_t aBase0 = sbase + A_OFF + g * 9216 +
        (uint32_t)((lane & 15) * 144 + (lane >> 4) * 16);
    const uint32_t bBase = sbase + B_OFF +
        (uint32_t)((wn * 64 + (lane & 7)) * 144 + ((lane >> 3) & 1) * 16);

    auto mma_chunk = [&](int kc) {
        const uint32_t aB = aBase0 + (kc & 1) * A_BUF;
        const uint32_t bC = bBase + kc * B_CHUNK;
#pragma unroll
        for (int k16 = 0; k16 < 4; k16++) {
            const uint32_t koff = k16 * 32;
            uint32_t ah[4][4], bb[8][2];
#pragma unroll
            for (int mt = 0; mt < 4; mt++)
                LDSM_X4(ah[mt][0], ah[mt][1], ah[mt][2], ah[mt][3],
                        aB + mt * 2304 + koff);
#pragma unroll
            for (int nt = 0; nt < 8; nt++)
                LDSM_X2(bb[nt][0], bb[nt][1], bC + nt * 1152 + koff);
#pragma unroll
            for (int mt = 0; mt < 4; mt++)
#pragma unroll
                for (int nt = 0; nt < 8; nt++)
                    MMA16816F16(acc[mt][nt], ah[mt], bb[nt]);
        }
    };

    produce(0, 0);
    CP_WAIT(0);
    __syncthreads();
#pragma unroll
    for (int kc = 0; kc < 4; kc++) {
        mma_chunk(kc);
        if (kc < 3) produce(kc + 1, (kc + 1) & 1);
        __syncthreads();
    }

    float b2c[16], gc[16], bc[16];
#pragma unroll
    for (int nt = 0; nt < 8; nt++) {
        int j0 = wn * 64 + nt * 8 + (lane & 3) * 2;
        b2c[2 * nt]     = sF[CONST_B2 + j0];
        b2c[2 * nt + 1] = sF[CONST_B2 + j0 + 1];
        gc[2 * nt]      = sF[CONST_L2G + j0];
        gc[2 * nt + 1]  = sF[CONST_L2G + j0 + 1];
        bc[2 * nt]      = sF[CONST_L2B + j0];
        bc[2 * nt + 1]  = sF[CONST_L2B + j0 + 1];
    }

#pragma unroll
    for (int mt = 0; mt < 4; mt++) {
#pragma unroll
        for (int h = 0; h < 2; h++) {
            float s1 = 0.f, s2 = 0.f;
#pragma unroll
            for (int nt = 0; nt < 8; nt++) {
                float y0 = acc[mt][nt][2 * h]     + b2c[2 * nt];
                float y1 = acc[mt][nt][2 * h + 1] + b2c[2 * nt + 1];
                acc[mt][nt][2 * h]     = y0;
                acc[mt][nt][2 * h + 1] = y1;
                s1 += y0 + y1;
                s2 += y0 * y0 + y1 * y1;
            }
            s1 += __shfl_xor_sync(~0u, s1, 1);
            s1 += __shfl_xor_sync(~0u, s1, 2);
            s2 += __shfl_xor_sync(~0u, s2, 1);
            s2 += __shfl_xor_sync(~0u, s2, 2);
            if ((lane & 3) == 0) {
                int r = mt * 16 + (lane >> 2) + 8 * h;
                sF[SR1_OFF + g * 256 + r * 4 + wn] = s1;
                sF[SR2_OFF + g * 256 + r * 4 + wn] = s2;
            }
        }
    }
    __syncthreads();
    if (wg_tid < 64) {
        int base = SR1_OFF + g * 256 + wg_tid * 4;
        float s1 = sF[base] + sF[base + 1] + sF[base + 2] + sF[base + 3];
        int base2 = SR2_OFF + g * 256 + wg_tid * 4;
        float s2 = sF[base2] + sF[base2 + 1] + sF[base2 + 2] + sF[base2 + 3];
        float mu = s1 * (1.f / DH);
        float vr = s2 * (1.f / DH) - mu * mu;
        sF[SMU_OFF + g * 64 + wg_tid] = mu;
        sF[SIS_OFF + g * 64 + wg_tid] = rsqrtf(vr + LN_EPS);
    }
    __syncthreads();

#pragma unroll
    for (int mt = 0; mt < 4; mt++) {
#pragma unroll
        for (int h = 0; h < 2; h++) {
            int r = mt * 16 + (lane >> 2) + 8 * h;
            float mu = sF[SMU_OFF + g * 64 + r];
            float is = sF[SIS_OFF + g * 64 + r];
            int fr = fbase + g * 64 + r;
            float* zp = g_znodes + ((size_t)fr * NQ + s) * DH;
#pragma unroll
            for (int nt = 0; nt < 8; nt++) {
                float z0 = (acc[mt][nt][2 * h]     - mu) * is * gc[2 * nt]     + bc[2 * nt];
                float z1 = (acc[mt][nt][2 * h + 1] - mu) * is * gc[2 * nt + 1] + bc[2 * nt + 1];
                *(float2*)(zp + wn * 64 + nt * 8 + (lane & 3) * 2) =
                    make_float2(z0, z1);
            }
        }
    }
}

// ======================= Chebyshev transform (NQ nodes, folded) ============
// c_j for j < NQ; slots [NQ, NNODES) written as exact zeros.
__global__ void __launch_bounds__(256) cheb_transform() {
    __shared__ float cosm[NQ * (NQ / 2)];   // [j][s<12]
    int tid = threadIdx.x;
#pragma unroll
    for (int i = 0; i < 2; i++) {
        int e = tid + i * 256;
        if (e < NQ * (NQ / 2)) {
            int j = e / (NQ / 2), sx = e % (NQ / 2);
            cosm[e] = cospif((float)(j * (2 * sx + 1)) / (2.0f * NQ));
        }
    }
    __syncthreads();

    int f = blockIdx.x;
    const float* zb = g_znodes + (size_t)f * NQ * DH + tid;
    float ze[NQ / 2], zo[NQ / 2];
#pragma unroll
    for (int sx = 0; sx < NQ / 2; sx++) {
        float zl = zb[sx * DH];
        float zh = zb[(NQ - 1 - sx) * DH];
        ze[sx] = zl + zh;
        zo[sx] = zl - zh;
    }

    float c0 = 0.f;
#pragma unroll
    for (int sx = 0; sx < NQ / 2; sx++) c0 += ze[sx];
    c0 *= (1.0f / NQ);
    atomicAdd(&g_c0[tid], c0);

    float cj[NNODES];
    cj[0] = 0.f;   // j=0 handled exactly via g_c0
#pragma unroll
    for (int j = 1; j < NQ; j++) {
        const float* zz = (j & 1) ? zo : ze;
        float c = 0.f;
#pragma unroll
        for (int sx = 0; sx < NQ / 2; sx++)
            c = fmaf(zz[sx], cosm[j * (NQ / 2) + sx], c);
        cj[j] = c * (2.0f / NQ);
    }
#pragma unroll
    for (int j = NQ; j < NNODES; j++) cj[j] = 0.f;
    uint32_t u[NNODES / 2];
#pragma unroll
    for (int i = 0; i < NNODES / 2; i++)
        u[i] = pack_f16(cj[2 * i], cj[2 * i + 1]);
    uint4* dst = (uint4*)(g_cT + (size_t)tid * (FF * NNODES) + f * NNODES);
#pragma unroll
    for (int i = 0; i < 4; i++)
        dst[i] = make_uint4(u[4 * i], u[4 * i + 1], u[4 * i + 2], u[4 * i + 3]);
}

// ======================= final GEMM: aggT[256,512] = C_T @ T^T ==========
// T computed ON THE FLY from g_acts (Chebyshev recurrence).
constexpr int FG_A0 = 0;
constexpr int FG_A1 = 18432;
constexpr int FG_B0 = 36864;
constexpr int FG_B1 = 73728;
constexpr int FG_SMEM = 110592;
constexpr int KTOT = FF * NNODES;

__global__ void __launch_bounds__(256, 1) gemm_final() {
    extern __shared__ char smem[];
    const uint32_t sbase = smem_to_u32(smem);
    const int tid = threadIdx.x, lane = tid & 31, wid = tid >> 5;
    const int mtile = blockIdx.x & 1;
    const int ntile = (blockIdx.x >> 1) & 1;
    const int ks = blockIdx.x >> 2;
    const int k0 = ks * 2048;
    const int g = wid >> 2, wn = wid & 3;

    auto loadA = [&](int kc, int buf) {
        uint32_t dst = sbase + (buf ? FG_A1 : FG_A0);
#pragma unroll
        for (int q = 0; q < 4; q++) {
            int i2 = tid + q * 256;
            int row = i2 >> 3, seg = i2 & 7;
            const char* src = (const char*)(g_cT +
                (size_t)(mtile * 128 + row) * KTOT + k0 + kc * 64 + seg * 8);
            CP_ASYNC16(dst + row * 144 + seg * 16, src);
        }
    };

    auto produceB = [&](int kc, int buf) {
        char* dstBase = smem + (buf ? FG_B1 : FG_B0);
        const int fbase2 = ks * 64 + kc * 2;
#pragma unroll
        for (int q = 0; q < 2; q++) {
            int p = tid + q * 256;
            int r = p >> 1, fh = p & 1;
            int f = fbase2 + fh;
            float a = g_acts[(size_t)(ntile * 256 + r) * FF + f];
            float x = (a - g_cf[f]) * g_ihf[f];
            x = fminf(1.f, fmaxf(-1.f, x));
            float T[NNODES];
            T[0] = 1.f; T[1] = x;
            float x2 = 2.f * x;
#pragma unroll
            for (int j = 2; j < NNODES; j++) T[j] = fmaf(x2, T[j - 1], -T[j - 2]);
            uint32_t u[NNODES / 2];
#pragma unroll
            for (int i = 0; i < NNODES / 2; i++)
                u[i] = pack_f16(T[2 * i], T[2 * i + 1]);
            char* d = dstBase + r * 144 + fh * 64;
#pragma unroll
            for (int i = 0; i < 4; i++)
                *(uint4*)(d + i * 16) =
                    make_uint4(u[4 * i], u[4 * i + 1], u[4 * i + 2], u[4 * i + 3]);
        }
    };

    float acc[4][8][4];
#pragma unroll
    for (int mt = 0; mt < 4; mt++)
#pragma unroll
        for (int nt = 0; nt < 8; nt++)
#pragma unroll
            for (int i = 0; i < 4; i++) acc[mt][nt][i] = 0.f;

    const uint32_t aBase0 = sbase + FG_A0 +
        (uint32_t)((g * 64 + (lane & 15)) * 144 + (lane >> 4) * 16);
    const uint32_t bBase0 = sbase + FG_B0 +
        (uint32_t)((wn * 64 + (lane & 7)) * 144 + ((lane >> 3) & 1) * 16);

    auto mma_chunk = [&](int kc) {
        const uint32_t aB = aBase0 + (kc & 1) * (FG_A1 - FG_A0);
        const uint32_t bC = bBase0 + (kc & 1) * (FG_B1 - FG_B0);
#pragma unroll
        for (int k16 = 0; k16 < 4; k16++) {
            const uint32_t koff = k16 * 32;
            uint32_t ah[4][4], bb[8][2];
#pragma unroll
            for (int mt = 0; mt < 4; mt++)
                LDSM_X4(ah[mt][0], ah[mt][1], ah[mt][2], ah[mt][3],
                        aB + mt * 2304 + koff);
#pragma unroll
            for (int nt = 0; nt < 8; nt++)
                LDSM_X2(bb[nt][0], bb[nt][1], bC + nt * 1152 + koff);
#pragma unroll
            for (int mt = 0; mt < 4; mt++)
#pragma unroll
                for (int nt = 0; nt < 8; nt++)
                    MMA16816F16(acc[mt][nt], ah[mt], bb[nt]);
        }
    };

    loadA(0, 0); CP_COMMIT();
    produceB(0, 0);
    CP_WAIT(0);
    __syncthreads();
#pragma unroll 1
    for (int kc = 0; kc < 32; kc++) {
        if (kc < 31) { loadA(kc + 1, (kc + 1) & 1); CP_COMMIT(); }
        mma_chunk(kc);
        if (kc < 31) {
            produceB(kc + 1, (kc + 1) & 1);
            CP_WAIT(0);
        }
        __syncthreads();
    }

#pragma unroll
    for (int mt = 0; mt < 4; mt++) {
#pragma unroll
        for (int h = 0; h < 2; h++) {
            int row = mtile * 128 + g * 64 + mt * 16 + (lane >> 2) + 8 * h;
#pragma unroll
            for (int nt = 0; nt < 8; nt++) {
#pragma unroll
                for (int e = 0; e < 2; e++) {
                    int col = ntile * 256 + wn * 64 + nt * 8 + (lane & 3) * 2 + e;
                    atomicAdd(&g_aggT[row * TOK + col], acc[mt][nt][2 * h + e]);
                }
            }
        }
    }
}

// ---------------- final LN over agg (transposed layout + c0) ------------
__global__ void __launch_bounds__(256) ln256_kernel(
    const float* __restrict__ g, const float* __restrict__ b)
{
    int t = blockIdx.x;
    int tid = threadIdx.x;
    int lane = tid & 31, wid = tid >> 5;
    float v = g_aggT[(size_t)tid * TOK + t] + g_c0[tid];
    float s1 = v, s2 = v * v;
#pragma unroll
    for (int o = 16; o; o >>= 1) {
        s1 += __shfl_xor_sync(~0u, s1, o);
        s2 += __shfl_xor_sync(~0u, s2, o);
    }
    __shared__ float r1[8], r2[8];
    if (lane == 0) { r1[wid] = s1; r2[wid] = s2; }
    __syncthreads();
    float t1 = 0.f, t2 = 0.f;
#pragma unroll
    for (int w = 0; w < 8; w++) { t1 += r1[w]; t2 += r2[w]; }
    float mean = t1 * (1.f / DH);
    float var = t2 * (1.f / DH) - mean * mean;
    float istd = rsqrtf(var + LN_EPS);
    g_r[t * DH + tid] = (v - mean) * istd * g[tid] + b[tid];
}

// ---------------- launch ----------------
extern "C" void kernel_launch(void* const* d_in, const int* in_sizes, int n_in,
                              void* d_out, int out_size)
{
    const float* x      = (const float*)d_in[0];
    const float* nv     = (const float*)d_in[1];
    const float* W_in   = (const float*)d_in[2];
    const float* phi_w1 = (const float*)d_in[3];
    const float* phi_b1 = (const float*)d_in[4];
    const float* ln1g   = (const float*)d_in[5];
    const float* ln1b   = (const float*)d_in[6];
    const float* phi_w2 = (const float*)d_in[7];
    const float* phi_b2 = (const float*)d_in[8];
    const float* ln2g   = (const float*)d_in[9];
    const float* ln2b   = (const float*)d_in[10];
    const float* rln_g  = (const float*)d_in[11];
    const float* rln_b  = (const float*)d_in[12];
    const float* rho_w1 = (const float*)d_in[13];
    const float* rho_b1 = (const float*)d_in[14];
    const float* rho_w2 = (const float*)d_in[15];
    const float* rho_b2 = (const float*)d_in[16];
    float* out = (float*)d_out;

    const int conv_total = TOK * DMODEL + FF * DMODEL + DH * DH;
    prep_conv<<<(conv_total + 255) / 256, 256>>>(x, W_in, phi_w2);      // 1

    cudaFuncSetAttribute(gemm_acts_f16,
                         cudaFuncAttributeMaxDynamicSharedMemorySize, GA_SMEM);
    gemm_acts_f16<<<dim3(8, 16), 256, GA_SMEM>>>();                     // 2

    gemm_nvproj<<<dim3(FF / 64, DH / 128), 256>>>(nv, phi_w1);          // 3

    // prep_f (FF+1 blocks) + coalesced range (64) + zero (512)
    prep_misc<<<FF + 1 + 64 + 512, 256>>>(phi_b1, phi_w1);              // 4

    cudaFuncSetAttribute(node_eval, cudaFuncAttributeMaxDynamicSharedMemorySize,
                         NE_SMEM);
    node_eval<<<16 * NQ, 256, NE_SMEM>>>(phi_b1, phi_w1, ln1g, ln1b,
                                         phi_b2, ln2g, ln2b);           // 5

    cheb_transform<<<FF, 256>>>();                                      // 6

    cudaFuncSetAttribute(gemm_final, cudaFuncAttributeMaxDynamicSharedMemorySize,
                         FG_SMEM);
    gemm_final<<<128, 256, FG_SMEM>>>();                                // 7

    ln256_kernel<<<TOK, 256>>>(rln_g, rln_b);                           // 8
    gemm_rho1<<<dim3(TOK / 64, DH2 / 128), 256>>>(rho_w1, rho_b1);      // 9
    gemm_rho2<<<dim3(TOK / 64, DMODEL / 128), 256>>>(rho_w2, rho_b2, out); // 10

    (void)in_sizes; (void)n_in; (void)out_size;
}

// round 17
// speedup vs baseline: 3.3610x; 1.4028x over previous
#include <cuda_runtime.h>
#include <cuda_fp16.h>
#include <math.h>
#include <stdint.h>

#define TOK 512
#define DMODEL 512
#define FF 2048
#define DN 128
#define DH 256
#define DH2 512
#define LN_EPS 1e-5f
#define NNODES 32   // coefficient slots (layout)
#define NQ 24       // quadrature nodes actually evaluated

// ---------------- scratch (no allocation allowed) ----------------
__device__ float g_acts[TOK * FF];
__device__ float g_nvproj[FF * DH];
__device__ float g_aggT[DH * TOK];          // [k][t]
__device__ float g_c0[DH];
__device__ __align__(16) __half g_rf16[TOK * DH];
__device__ __align__(16) __half g_r2f16[TOK * DH2];
__device__ __align__(16) __half g_w2f16[4][256 * 72];
__device__ __align__(16) __half g_xf16[TOK * DMODEL];
__device__ __align__(16) __half g_wf16[FF * DMODEL];
__device__ __align__(16) __half g_rw1f16[DH2 * DH];
__device__ __align__(16) __half g_rw2f16[DMODEL * DH2];
__device__ float4 g_fc[FF];                 // per-f LN1 constants
__device__ float g_wscal[2];
__device__ float g_cf[FF];                  // a-range center
__device__ float g_hf[FF];                  // a-range half width
__device__ float g_ihf[FF];                 // 1 / half width
__device__ __align__(16) __half g_znf16[FF * NQ * DH];
__device__ __align__(16) __half g_cT[DH * FF * NNODES];    // [k][f*32+j]

__device__ __forceinline__ float gelu_exact(float x) {
    return 0.5f * x * (1.0f + erff(x * 0.70710678118654752440f));
}

__device__ __forceinline__ uint32_t smem_to_u32(const void* p) {
    uint32_t a;
    asm("{ .reg .u64 t; cvta.to.shared.u64 t, %1; cvt.u32.u64 %0, t; }"
        : "=r"(a) : "l"(p));
    return a;
}

__device__ __forceinline__ uint32_t pack_f16(float e0, float e1) {
    uint32_t r;  // e0 -> low half
    asm("cvt.rn.f16x2.f32 %0, %1, %2;" : "=r"(r) : "f"(e1), "f"(e0));
    return r;
}

#define LDSM_X4(r0, r1, r2, r3, addr) \
    asm volatile("ldmatrix.sync.aligned.m8n8.x4.shared.b16 {%0,%1,%2,%3}, [%4];" \
        : "=r"(r0), "=r"(r1), "=r"(r2), "=r"(r3) : "r"(addr))
#define LDSM_X2(r0, r1, addr) \
    asm volatile("ldmatrix.sync.aligned.m8n8.x2.shared.b16 {%0,%1}, [%2];" \
        : "=r"(r0), "=r"(r1) : "r"(addr))
#define MMA16816F16(d, a, b) \
    asm volatile("mma.sync.aligned.m16n8k16.row.col.f32.f16.f16.f32 " \
        "{%0,%1,%2,%3}, {%4,%5,%6,%7}, {%8,%9}, {%0,%1,%2,%3};" \
        : "+f"((d)[0]), "+f"((d)[1]), "+f"((d)[2]), "+f"((d)[3]) \
        : "r"((a)[0]), "r"((a)[1]), "r"((a)[2]), "r"((a)[3]), \
          "r"((b)[0]), "r"((b)[1]))
#define CP_ASYNC16(dst, src) \
    asm volatile("cp.async.cg.shared.global [%0], [%1], 16;" \
        :: "r"(dst), "l"(src) : "memory")
#define CP_COMMIT() asm volatile("cp.async.commit_group;" ::: "memory")
#define CP_WAIT(n)  asm volatile("cp.async.wait_group %0;" :: "n"(n) : "memory")

// ======================= SIMT GEMM (nvproj only) ==================
__global__ void __launch_bounds__(256) gemm_nvproj(const float* __restrict__ nv,
                                                   const float* __restrict__ phi_w1)
{
    constexpr int BM = 64, BN = 128, BK = 32;
    const int lda = DN, ldb = DN + 1, ldc = DH, K = DN;
    const float* A = nv;
    const float* B = phi_w1;
    float* C = g_nvproj;
    __shared__ float sA[BK][BM + 2];
    __shared__ float sB[BK][BN + 2];
    int tid = threadIdx.x;
    int lane = tid & 31, wid = tid >> 5;
    int bm = blockIdx.x * BM, bn = blockIdx.y * BN;

    float acc[8][4];
#pragma unroll
    for (int i = 0; i < 8; i++)
#pragma unroll
        for (int u = 0; u < 4; u++) acc[i][u] = 0.f;

    for (int k0 = 0; k0 < K; k0 += BK) {
#pragma unroll
        for (int r = 0; r < 8; r++) {
            int m = wid + 8 * r;
            sA[lane][m] = A[(size_t)(bm + m) * lda + k0 + lane];
        }
#pragma unroll
        for (int r = 0; r < 16; r++) {
            int n = wid + 8 * r;
            sB[lane][n] = B[(size_t)(bn + n) * ldb + k0 + lane];
        }
        __syncthreads();
#pragma unroll
        for (int kk = 0; kk < BK; kk++) {
            float a[8], b[4];
#pragma unroll
            for (int i = 0; i < 8; i++) a[i] = sA[kk][wid * 8 + i];
#pragma unroll
            for (int u = 0; u < 4; u++) b[u] = sB[kk][lane + 32 * u];
#pragma unroll
            for (int i = 0; i < 8; i++)
#pragma unroll
                for (int u = 0; u < 4; u++) acc[i][u] += a[i] * b[u];
        }
        __syncthreads();
    }
#pragma unroll
    for (int i = 0; i < 8; i++) {
        int m = bm + wid * 8 + i;
#pragma unroll
        for (int u = 0; u < 4; u++) {
            int n = bn + lane + 32 * u;
            C[(size_t)m * ldc + n] = acc[i][u];
        }
    }
}

// ======================= generic fp16 tensor GEMM ==========================
// C[M,N] = act(A[M,K] @ B[N,K]^T + bias), A/B fp16 row-major, M tile 64,
// N tile 128, 256 threads. Optional fp32 out Cf, optional fp16 out Ch.
constexpr int GA_A_BUF = 9216;    // 64 x 144
constexpr int GA_B_OFF = 18432;
constexpr int GA_B_BUF = 18432;   // 128 x 144
constexpr int GA_SMEM  = 55296;

template <bool GELU>
__global__ void __launch_bounds__(256) gemm_f16_g(
    const __half* __restrict__ A, const __half* __restrict__ B,
    const float* __restrict__ bias, float* __restrict__ Cf,
    __half* __restrict__ Ch, int K, int N, int KC)
{
    extern __shared__ char smem[];
    const uint32_t sbase = smem_to_u32(smem);
    const int tid = threadIdx.x, lane = tid & 31, wid = tid >> 5;
    const int bm = blockIdx.x * 64, bn = blockIdx.y * 128;
    const int wm = wid & 1, wn = wid >> 1;

    auto loadA = [&](int kc, int buf) {
        uint32_t dst = sbase + buf * GA_A_BUF;
#pragma unroll
        for (int q = 0; q < 2; q++) {
            int i2 = tid + q * 256;
            int row = i2 >> 3, seg = i2 & 7;
            const char* src = (const char*)(A +
                (size_t)(bm + row) * K + kc * 64 + seg * 8);
            CP_ASYNC16(dst + row * 144 + seg * 16, src);
        }
    };
    auto loadB = [&](int kc, int buf) {
        uint32_t dst = sbase + GA_B_OFF + buf * GA_B_BUF;
#pragma unroll
        for (int q = 0; q < 4; q++) {
            int i2 = tid + q * 256;
            int row = i2 >> 3, seg = i2 & 7;
            const char* src = (const char*)(B +
                (size_t)(bn + row) * K + kc * 64 + seg * 8);
            CP_ASYNC16(dst + row * 144 + seg * 16, src);
        }
    };

    float acc[2][4][4];
#pragma unroll
    for (int mt = 0; mt < 2; mt++)
#pragma unroll
        for (int nt = 0; nt < 4; nt++)
#pragma unroll
            for (int i = 0; i < 4; i++) acc[mt][nt][i] = 0.f;

    const uint32_t aBase0 = sbase +
        (uint32_t)((wm * 32 + (lane & 15)) * 144 + (lane >> 4) * 16);
    const uint32_t bBase0 = sbase + GA_B_OFF +
        (uint32_t)((wn * 32 + (lane & 7)) * 144 + ((lane >> 3) & 1) * 16);

    loadA(0, 0); loadB(0, 0); CP_COMMIT();
#pragma unroll 1
    for (int kc = 0; kc < KC; kc++) {
        if (kc < KC - 1) {
            loadA(kc + 1, (kc + 1) & 1);
            loadB(kc + 1, (kc + 1) & 1);
            CP_COMMIT();
            CP_WAIT(1);
        } else {
            CP_WAIT(0);
        }
        __syncthreads();
        const uint32_t aB = aBase0 + (kc & 1) * GA_A_BUF;
        const uint32_t bC = bBase0 + (kc & 1) * GA_B_BUF;
#pragma unroll
        for (int k16 = 0; k16 < 4; k16++) {
            const uint32_t koff = k16 * 32;
            uint32_t ah[2][4], bb[4][2];
#pragma unroll
            for (int mt = 0; mt < 2; mt++)
                LDSM_X4(ah[mt][0], ah[mt][1], ah[mt][2], ah[mt][3],
                        aB + mt * 2304 + koff);
#pragma unroll
            for (int nt = 0; nt < 4; nt++)
                LDSM_X2(bb[nt][0], bb[nt][1], bC + nt * 1152 + koff);
#pragma unroll
            for (int mt = 0; mt < 2; mt++)
#pragma unroll
                for (int nt = 0; nt < 4; nt++)
                    MMA16816F16(acc[mt][nt], ah[mt], bb[nt]);
        }
        __syncthreads();
    }

#pragma unroll
    for (int mt = 0; mt < 2; mt++) {
#pragma unroll
        for (int h = 0; h < 2; h++) {
            int m = bm + wm * 32 + mt * 16 + (lane >> 2) + 8 * h;
#pragma unroll
            for (int nt = 0; nt < 4; nt++) {
                int n = bn + wn * 32 + nt * 8 + (lane & 3) * 2;
                float v0 = acc[mt][nt][2 * h];
                float v1 = acc[mt][nt][2 * h + 1];
                if (bias) { v0 += bias[n]; v1 += bias[n + 1]; }
                if (GELU) { v0 = gelu_exact(v0); v1 = gelu_exact(v1); }
                if (Cf) *(float2*)&Cf[(size_t)m * N + n] = make_float2(v0, v1);
                if (Ch) *(uint32_t*)&Ch[(size_t)m * N + n] = pack_f16(v0, v1);
            }
        }
    }
}

// ======================= fused convert prep =======================
__global__ void __launch_bounds__(256) prep_conv(const float* __restrict__ x,
                                                 const float* __restrict__ W_in,
                                                 const float* __restrict__ w2,
                                                 const float* __restrict__ rw1,
                                                 const float* __restrict__ rw2) {
    int idx = blockIdx.x * 256 + threadIdx.x;
    if (idx < TOK * DMODEL) g_xf16[idx] = __float2half(x[idx]);
    int i2 = idx - TOK * DMODEL;
    if (i2 >= 0 && i2 < FF * DMODEL) g_wf16[i2] = __float2half(W_in[i2]);
    int i3 = i2 - FF * DMODEL;
    if (i3 >= 0 && i3 < DH * DH) {
        int j = i3 >> 8, k = i3 & 255;
        int kc = k >> 6, kin = k & 63;
        g_w2f16[kc][j * 72 + kin] = __float2half(w2[i3]);
    }
    int i4 = i3 - DH * DH;
    if (i4 >= 0 && i4 < DH2 * DH) g_rw1f16[i4] = __float2half(rw1[i4]);
    int i5 = i4 - DH2 * DH;
    if (i5 >= 0 && i5 < DMODEL * DH2) g_rw2f16[i5] = __float2half(rw2[i5]);
}

// ======================= fused prep: prep_f + range + zero =================
__global__ void __launch_bounds__(256) prep_misc(const float* __restrict__ phi_b1,
                                                 const float* __restrict__ phi_w1) {
    int bid = blockIdx.x;
    int tid = threadIdx.x, lane = tid & 31, wid = tid >> 5;

    if (bid <= FF) {
        float w = phi_w1[tid * (DN + 1) + DN];
        if (bid == FF) {
            float s0 = w, s1 = w * w;
#pragma unroll
            for (int o = 16; o; o >>= 1) {
                s0 += __shfl_xor_sync(~0u, s0, o);
                s1 += __shfl_xor_sync(~0u, s1, o);
            }
            __shared__ float r0[8], r1[8];
            if (lane == 0) { r0[wid] = s0; r1[wid] = s1; }
            __syncthreads();
            if (tid == 0) {
                float t0 = 0.f, t1 = 0.f;
                for (int i = 0; i < 8; i++) { t0 += r0[i]; t1 += r1[i]; }
                g_wscal[0] = t0 * (1.f / DH);
                g_wscal[1] = t1 * (1.f / DH);
            }
            return;
        }
        int f = bid;
        float p = g_nvproj[f * DH + tid] + phi_b1[tid];
        float s0 = p, s1 = p * p, s2 = p * w;
#pragma unroll
        for (int o = 16; o; o >>= 1) {
            s0 += __shfl_xor_sync(~0u, s0, o);
            s1 += __shfl_xor_sync(~0u, s1, o);
            s2 += __shfl_xor_sync(~0u, s2, o);
        }
        __shared__ float r0[8], r1[8], r2[8];
        if (lane == 0) { r0[wid] = s0; r1[wid] = s1; r2[wid] = s2; }
        __syncthreads();
        if (tid == 0) {
            float t0 = 0.f, t1 = 0.f, t2 = 0.f;
            for (int i = 0; i < 8; i++) { t0 += r0[i]; t1 += r1[i]; t2 += r2[i]; }
            g_fc[f] = make_float4(t0 * (1.f / DH), t1 * (1.f / DH),
                                  t2 * (1.f / DH), 0.f);
        }
        return;
    }

    int b2 = bid - FF - 1;
    if (b2 < 64) {
        int f0 = b2 * 32;
        float mn = 3.4e38f, mx = -3.4e38f;
        const float* base = g_acts + f0 + lane;
        for (int r = wid * 64; r < wid * 64 + 64; r++) {
            float v = base[(size_t)r * FF];
            mn = fminf(mn, v); mx = fmaxf(mx, v);
        }
        __shared__ float smn[8][32], smx[8][32];
        smn[wid][lane] = mn; smx[wid][lane] = mx;
        __syncthreads();
        if (tid < 32) {
            float a = smn[0][tid], b = smx[0][tid];
#pragma unroll
            for (int i = 1; i < 8; i++) {
                a = fminf(a, smn[i][tid]);
                b = fmaxf(b, smx[i][tid]);
            }
            float c = 0.5f * (b + a), h = 0.5f * (b - a) + 1e-6f;
            int f = f0 + tid;
            g_cf[f] = c; g_hf[f] = h; g_ihf[f] = 1.0f / h;
        }
    } else {
        int i = (b2 - 64) * 256 + tid;
        if (i < DH * TOK) g_aggT[i] = 0.f;
        if (i < DH) g_c0[i] = 0.f;
    }
}

// ======================= node evaluation =====================
constexpr int CONST_B1   = 0;
constexpr int CONST_WACT = 256;
constexpr int CONST_L1G  = 512;
constexpr int CONST_L1B  = 768;
constexpr int CONST_B2   = 1024;
constexpr int CONST_L2G  = 1280;
constexpr int CONST_L2B  = 1536;
constexpr int SR1_OFF    = 1792;
constexpr int SR2_OFF    = 2304;
constexpr int SMU_OFF    = 2816;
constexpr int SIS_OFF    = 2944;
constexpr int A_OFF      = 12288;
constexpr int A_BUF      = 18432;
constexpr int B_OFF      = A_OFF + 2 * A_BUF;
constexpr int B_CHUNK    = 36864;
constexpr int NE_SMEM    = B_OFF + 4 * B_CHUNK;   // 196608

__global__ void __launch_bounds__(256, 1) node_eval(
    const float* __restrict__ phi_b1, const float* __restrict__ phi_w1,
    const float* __restrict__ ln1g, const float* __restrict__ ln1b,
    const float* __restrict__ b2, const float* __restrict__ ln2g,
    const float* __restrict__ ln2b)
{
    extern __shared__ char smem[];
    float* sF = (float*)smem;
    const uint32_t sbase = smem_to_u32(smem);

    const int tid = threadIdx.x, lane = tid & 31, wid = tid >> 5;
    const int fg = blockIdx.x & 15;
    const int s  = blockIdx.x >> 4;          // 0..NQ-1
    const int fbase = fg * 128;
    const float xs = cospif((float)(2 * s + 1) / (2.0f * NQ));

    {
        uint32_t dst = sbase + B_OFF + tid * 16;
        const char* src = (const char*)g_w2f16 + tid * 16;
#pragma unroll
        for (int i = 0; i < 36; i++)
            CP_ASYNC16(dst + i * 4096, src + i * 4096);
        CP_COMMIT();
    }

    sF[CONST_B1 + tid]   = phi_b1[tid];
    sF[CONST_WACT + tid] = phi_w1[tid * (DN + 1) + DN];
    sF[CONST_L1G + tid]  = ln1g[tid];
    sF[CONST_L1B + tid]  = ln1b[tid];
    sF[CONST_B2 + tid]   = b2[tid];
    sF[CONST_L2G + tid]  = ln2g[tid];
    sF[CONST_L2B + tid]  = ln2b[tid];
    __syncthreads();

    const int g = wid >> 2, wn = wid & 3;
    const int wg_tid = tid & 127;

    const int row = wg_tid >> 1;
    const int khalf = wg_tid & 1;
    const int f = fbase + g * 64 + row;
    const float a = g_cf[f] + g_hf[f] * xs;
    const float4 fc = g_fc[f];
    const float mean = fc.x + a * g_wscal[0];
    const float e2 = fc.y + 2.f * a * fc.z + a * a * g_wscal[1];
    const float istd = rsqrtf(e2 - mean * mean + LN_EPS);
    const float nmi = -mean * istd;

    char* const aDst0 = smem + A_OFF + g * 9216 + row * 144 + khalf * 64;
    const float* const nvRow = g_nvproj + (size_t)f * DH + khalf * 32;

    auto produce = [&](int kc, int buf) {
        const float* nvp = nvRow + kc * 64;
        char* aDst = aDst0 + buf * A_BUF;
#pragma unroll 2
        for (int u = 0; u < 8; u++) {
            float4 pv = *(const float4*)(nvp + u * 4);
            float p4[4] = {pv.x, pv.y, pv.z, pv.w};
            float gv[4];
            int kb = kc * 64 + khalf * 32 + u * 4;
#pragma unroll
            for (int e = 0; e < 4; e++) {
                int k = kb + e;
                float val = fmaf(a, sF[CONST_WACT + k], p4[e] + sF[CONST_B1 + k]);
                float sc = fmaf(val, istd, nmi);
                float xx = fmaf(sc, sF[CONST_L1G + k], sF[CONST_L1B + k]);
                gv[e] = gelu_exact(xx);
            }
            *(uint2*)(aDst + u * 8) =
                make_uint2(pack_f16(gv[0], gv[1]), pack_f16(gv[2], gv[3]));
        }
    };

    float acc[4][8][4];
#pragma unroll
    for (int mt = 0; mt < 4; mt++)
#pragma unroll
        for (int nt = 0; nt < 8; nt++)
#pragma unroll
            for (int i = 0; i < 4; i++) acc[mt][nt][i] = 0.f;

    const uint32_t aBase0 = sbase + A_OFF + g * 9216 +
        (uint32_t)((lane & 15) * 144 + (lane >> 4) * 16);
    const uint32_t bBase = sbase + B_OFF +
        (uint32_t)((wn * 64 + (lane & 7)) * 144 + ((lane >> 3) & 1) * 16);

    auto mma_chunk = [&](int kc) {
        const uint32_t aB = aBase0 + (kc & 1) * A_BUF;
        const uint32_t bC = bBase + kc * B_CHUNK;
#pragma unroll
        for (int k16 = 0; k16 < 4; k16++) {
            const uint32_t koff = k16 * 32;
            uint32_t ah[4][4], bb[8][2];
#pragma unroll
            for (int mt = 0; mt < 4; mt++)
                LDSM_X4(ah[mt][0], ah[mt][1], ah[mt][2], ah[mt][3],
                        aB + mt * 2304 + koff);
#pragma unroll
            for (int nt = 0; nt < 8; nt++)
                LDSM_X2(bb[nt][0], bb[nt][1], bC + nt * 1152 + koff);
#pragma unroll
            for (int mt = 0; mt < 4; mt++)
#pragma unroll
                for (int nt = 0; nt < 8; nt++)
                    MMA16816F16(acc[mt][nt], ah[mt], bb[nt]);
        }
    };

    produce(0, 0);
    CP_WAIT(0);
    __syncthreads();
#pragma unroll
    for (int kc = 0; kc < 4; kc++) {
        mma_chunk(kc);
        if (kc < 3) produce(kc + 1, (kc + 1) & 1);
        __syncthreads();
    }

    float b2c[16], gc[16], bc[16];
#pragma unroll
    for (int nt = 0; nt < 8; nt++) {
        int j0 = wn * 64 + nt * 8 + (lane & 3) * 2;
        b2c[2 * nt]     = sF[CONST_B2 + j0];
        b2c[2 * nt + 1] = sF[CONST_B2 + j0 + 1];
        gc[2 * nt]      = sF[CONST_L2G + j0];
        gc[2 * nt + 1]  = sF[CONST_L2G + j0 + 1];
        bc[2 * nt]      = sF[CONST_L2B + j0];
        bc[2 * nt + 1]  = sF[CONST_L2B + j0 + 1];
    }

#pragma unroll
    for (int mt = 0; mt < 4; mt++) {
#pragma unroll
        for (int h = 0; h < 2; h++) {
            float s1 = 0.f, s2 = 0.f;
#pragma unroll
            for (int nt = 0; nt < 8; nt++) {
                float y0 = acc[mt][nt][2 * h]     + b2c[2 * nt];
                float y1 = acc[mt][nt][2 * h + 1] + b2c[2 * nt + 1];
                acc[mt][nt][2 * h]     = y0;
                acc[mt][nt][2 * h + 1] = y1;
                s1 += y0 + y1;
                s2 += y0 * y0 + y1 * y1;
            }
            s1 += __shfl_xor_sync(~0u, s1, 1);
            s1 += __shfl_xor_sync(~0u, s1, 2);
            s2 += __shfl_xor_sync(~0u, s2, 1);
            s2 += __shfl_xor_sync(~0u, s2, 2);
            if ((lane & 3) == 0) {
                int r = mt * 16 + (lane >> 2) + 8 * h;
                sF[SR1_OFF + g * 256 + r * 4 + wn] = s1;
                sF[SR2_OFF + g * 256 + r * 4 + wn] = s2;
            }
        }
    }
    __syncthreads();
    if (wg_tid < 64) {
        int base = SR1_OFF + g * 256 + wg_tid * 4;
        float s1 = sF[base] + sF[base + 1] + sF[base + 2] + sF[base + 3];
        int base2 = SR2_OFF + g * 256 + wg_tid * 4;
        float s2 = sF[base2] + sF[base2 + 1] + sF[base2 + 2] + sF[base2 + 3];
        float mu = s1 * (1.f / DH);
        float vr = s2 * (1.f / DH) - mu * mu;
        sF[SMU_OFF + g * 64 + wg_tid] = mu;
        sF[SIS_OFF + g * 64 + wg_tid] = rsqrtf(vr + LN_EPS);
    }
    __syncthreads();

#pragma unroll
    for (int mt = 0; mt < 4; mt++) {
#pragma unroll
        for (int h = 0; h < 2; h++) {
            int r = mt * 16 + (lane >> 2) + 8 * h;
            float mu = sF[SMU_OFF + g * 64 + r];
            float is = sF[SIS_OFF + g * 64 + r];
            int fr = fbase + g * 64 + r;
            __half* zp = g_znf16 + ((size_t)fr * NQ + s) * DH;
#pragma unroll
            for (int nt = 0; nt < 8; nt++) {
                float z0 = (acc[mt][nt][2 * h]     - mu) * is * gc[2 * nt]     + bc[2 * nt];
                float z1 = (acc[mt][nt][2 * h + 1] - mu) * is * gc[2 * nt + 1] + bc[2 * nt + 1];
                *(uint32_t*)(zp + wn * 64 + nt * 8 + (lane & 3) * 2) =
                    pack_f16(z0, z1);
            }
        }
    }
}

// ======================= Chebyshev transform (NQ nodes, folded) ============
__global__ void __launch_bounds__(256) cheb_transform() {
    __shared__ float cosm[NQ * (NQ / 2)];   // [j][s<12]
    int tid = threadIdx.x;
#pragma unroll
    for (int i = 0; i < 2; i++) {
        int e = tid + i * 256;
        if (e < NQ * (NQ / 2)) {
            int j = e / (NQ / 2), sx = e % (NQ / 2);
            cosm[e] = cospif((float)(j * (2 * sx + 1)) / (2.0f * NQ));
        }
    }
    __syncthreads();

    int f = blockIdx.x;
    const __half* zb = g_znf16 + (size_t)f * NQ * DH + tid;
    float ze[NQ / 2], zo[NQ / 2];
#pragma unroll
    for (int sx = 0; sx < NQ / 2; sx++) {
        float zl = __half2float(zb[sx * DH]);
        float zh = __half2float(zb[(NQ - 1 - sx) * DH]);
        ze[sx] = zl + zh;
        zo[sx] = zl - zh;
    }

    float c0 = 0.f;
#pragma unroll
    for (int sx = 0; sx < NQ / 2; sx++) c0 += ze[sx];
    c0 *= (1.0f / NQ);
    atomicAdd(&g_c0[tid], c0);

    float cj[NNODES];
    cj[0] = 0.f;   // j=0 handled exactly via g_c0
#pragma unroll
    for (int j = 1; j < NQ; j++) {
        const float* zz = (j & 1) ? zo : ze;
        float c = 0.f;
#pragma unroll
        for (int sx = 0; sx < NQ / 2; sx++)
            c = fmaf(zz[sx], cosm[j * (NQ / 2) + sx], c);
        cj[j] = c * (2.0f / NQ);
    }
#pragma unroll
    for (int j = NQ; j < NNODES; j++) cj[j] = 0.f;
    uint32_t u[NNODES / 2];
#pragma unroll
    for (int i = 0; i < NNODES / 2; i++)
        u[i] = pack_f16(cj[2 * i], cj[2 * i + 1]);
    uint4* dst = (uint4*)(g_cT + (size_t)tid * (FF * NNODES) + f * NNODES);
#pragma unroll
    for (int i = 0; i < 4; i++)
        dst[i] = make_uint4(u[4 * i], u[4 * i + 1], u[4 * i + 2], u[4 * i + 3]);
}

// ======================= final GEMM: aggT[256,512] = C_T @ T^T ==========
constexpr int FG_A0 = 0;
constexpr int FG_A1 = 18432;
constexpr int FG_B0 = 36864;
constexpr int FG_B1 = 73728;
constexpr int FG_SMEM = 110592;
constexpr int KTOT = FF * NNODES;

__global__ void __launch_bounds__(256, 1) gemm_final() {
    extern __shared__ char smem[];
    const uint32_t sbase = smem_to_u32(smem);
    const int tid = threadIdx.x, lane = tid & 31, wid = tid >> 5;
    const int mtile = blockIdx.x & 1;
    const int ntile = (blockIdx.x >> 1) & 1;
    const int ks = blockIdx.x >> 2;
    const int k0 = ks * 2048;
    const int g = wid >> 2, wn = wid & 3;

    auto loadA = [&](int kc, int buf) {
        uint32_t dst = sbase + (buf ? FG_A1 : FG_A0);
#pragma unroll
        for (int q = 0; q < 4; q++) {
            int i2 = tid + q * 256;
            int row = i2 >> 3, seg = i2 & 7;
            const char* src = (const char*)(g_cT +
                (size_t)(mtile * 128 + row) * KTOT + k0 + kc * 64 + seg * 8);
            CP_ASYNC16(dst + row * 144 + seg * 16, src);
        }
    };

    auto produceB = [&](int kc, int buf) {
        char* dstBase = smem + (buf ? FG_B1 : FG_B0);
        const int fbase2 = ks * 64 + kc * 2;
#pragma unroll
        for (int q = 0; q < 2; q++) {
            int p = tid + q * 256;
            int r = p >> 1, fh = p & 1;
            int f = fbase2 + fh;
            float a = g_acts[(size_t)(ntile * 256 + r) * FF + f];
            float x = (a - g_cf[f]) * g_ihf[f];
            x = fminf(1.f, fmaxf(-1.f, x));
            float T[NNODES];
            T[0] = 1.f; T[1] = x;
            float x2 = 2.f * x;
#pragma unroll
            for (int j = 2; j < NNODES; j++) T[j] = fmaf(x2, T[j - 1], -T[j - 2]);
            uint32_t u[NNODES / 2];
#pragma unroll
            for (int i = 0; i < NNODES / 2; i++)
                u[i] = pack_f16(T[2 * i], T[2 * i + 1]);
            char* d = dstBase + r * 144 + fh * 64;
#pragma unroll
            for (int i = 0; i < 4; i++)
                *(uint4*)(d + i * 16) =
                    make_uint4(u[4 * i], u[4 * i + 1], u[4 * i + 2], u[4 * i + 3]);
        }
    };

    float acc[4][8][4];
#pragma unroll
    for (int mt = 0; mt < 4; mt++)
#pragma unroll
        for (int nt = 0; nt < 8; nt++)
#pragma unroll
            for (int i = 0; i < 4; i++) acc[mt][nt][i] = 0.f;

    const uint32_t aBase0 = sbase + FG_A0 +
        (uint32_t)((g * 64 + (lane & 15)) * 144 + (lane >> 4) * 16);
    const uint32_t bBase0 = sbase + FG_B0 +
        (uint32_t)((wn * 64 + (lane & 7)) * 144 + ((lane >> 3) & 1) * 16);

    auto mma_chunk = [&](int kc) {
        const uint32_t aB = aBase0 + (kc & 1) * (FG_A1 - FG_A0);
        const uint32_t bC = bBase0 + (kc & 1) * (FG_B1 - FG_B0);
#pragma unroll
        for (int k16 = 0; k16 < 4; k16++) {
            const uint32_t koff = k16 * 32;
            uint32_t ah[4][4], bb[8][2];
#pragma unroll
            for (int mt = 0; mt < 4; mt++)
                LDSM_X4(ah[mt][0], ah[mt][1], ah[mt][2], ah[mt][3],
                        aB + mt * 2304 + koff);
#pragma unroll
            for (int nt = 0; nt < 8; nt++)
                LDSM_X2(bb[nt][0], bb[nt][1], bC + nt * 1152 + koff);
#pragma unroll
            for (int mt = 0; mt < 4; mt++)
#pragma unroll
                for (int nt = 0; nt < 8; nt++)
                    MMA16816F16(acc[mt][nt], ah[mt], bb[nt]);
        }
    };

    loadA(0, 0); CP_COMMIT();
    produceB(0, 0);
    CP_WAIT(0);
    __syncthreads();
#pragma unroll 1
    for (int kc = 0; kc < 32; kc++) {
        if (kc < 31) { loadA(kc + 1, (kc + 1) & 1); CP_COMMIT(); }
        mma_chunk(kc);
        if (kc < 31) {
            produceB(kc + 1, (kc + 1) & 1);
            CP_WAIT(0);
        }
        __syncthreads();
    }

#pragma unroll
    for (int mt = 0; mt < 4; mt++) {
#pragma unroll
        for (int h = 0; h < 2; h++) {
            int row = mtile * 128 + g * 64 + mt * 16 + (lane >> 2) + 8 * h;
#pragma unroll
            for (int nt = 0; nt < 8; nt++) {
#pragma unroll
                for (int e = 0; e < 2; e++) {
                    int col = ntile * 256 + wn * 64 + nt * 8 + (lane & 3) * 2 + e;
                    atomicAdd(&g_aggT[row * TOK + col], acc[mt][nt][2 * h + e]);
                }
            }
        }
    }
}

// ---------------- final LN over agg (transposed layout + c0) ------------
__global__ void __launch_bounds__(256) ln256_kernel(
    const float* __restrict__ g, const float* __restrict__ b)
{
    int t = blockIdx.x;
    int tid = threadIdx.x;
    int lane = tid & 31, wid = tid >> 5;
    float v = g_aggT[(size_t)tid * TOK + t] + g_c0[tid];
    float s1 = v, s2 = v * v;
#pragma unroll
    for (int o = 16; o; o >>= 1) {
        s1 += __shfl_xor_sync(~0u, s1, o);
        s2 += __shfl_xor_sync(~0u, s2, o);
    }
    __shared__ float r1[8], r2[8];
    if (lane == 0) { r1[wid] = s1; r2[wid] = s2; }
    __syncthreads();
    float t1 = 0.f, t2 = 0.f;
#pragma unroll
    for (int w = 0; w < 8; w++) { t1 += r1[w]; t2 += r2[w]; }
    float mean = t1 * (1.f / DH);
    float var = t2 * (1.f / DH) - mean * mean;
    float istd = rsqrtf(var + LN_EPS);
    g_rf16[t * DH + tid] =
        __float2half((v - mean) * istd * g[tid] + b[tid]);
}

// ---------------- launch ----------------
extern "C" void kernel_launch(void* const* d_in, const int* in_sizes, int n_in,
                              void* d_out, int out_size)
{
    const float* x      = (const float*)d_in[0];
    const float* nv     = (const float*)d_in[1];
    const float* W_in   = (const float*)d_in[2];
    const float* phi_w1 = (const float*)d_in[3];
    const float* phi_b1 = (const float*)d_in[4];
    const float* ln1g   = (const float*)d_in[5];
    const float* ln1b   = (const float*)d_in[6];
    const float* phi_w2 = (const float*)d_in[7];
    const float* phi_b2 = (const float*)d_in[8];
    const float* ln2g   = (const float*)d_in[9];
    const float* ln2b   = (const float*)d_in[10];
    const float* rln_g  = (const float*)d_in[11];
    const float* rln_b  = (const float*)d_in[12];
    const float* rho_w1 = (const float*)d_in[13];
    const float* rho_b1 = (const float*)d_in[14];
    const float* rho_w2 = (const float*)d_in[15];
    const float* rho_b2 = (const float*)d_in[16];
    float* out = (float*)d_out;

    __half *d_rf16, *d_r2f16, *d_xf16, *d_wf16, *d_rw1, *d_rw2;
    float *d_acts;
    cudaGetSymbolAddress((void**)&d_rf16, g_rf16);
    cudaGetSymbolAddress((void**)&d_r2f16, g_r2f16);
    cudaGetSymbolAddress((void**)&d_xf16, g_xf16);
    cudaGetSymbolAddress((void**)&d_wf16, g_wf16);
    cudaGetSymbolAddress((void**)&d_rw1, g_rw1f16);
    cudaGetSymbolAddress((void**)&d_rw2, g_rw2f16);
    cudaGetSymbolAddress((void**)&d_acts, g_acts);

    const int conv_total = TOK * DMODEL + FF * DMODEL + DH * DH +
                           DH2 * DH + DMODEL * DH2;
    prep_conv<<<(conv_total + 255) / 256, 256>>>(x, W_in, phi_w2,
                                                 rho_w1, rho_w2);       // 1

    cudaFuncSetAttribute(gemm_f16_g<true>,
                         cudaFuncAttributeMaxDynamicSharedMemorySize, GA_SMEM);
    cudaFuncSetAttribute(gemm_f16_g<false>,
                         cudaFuncAttributeMaxDynamicSharedMemorySize, GA_SMEM);

    // acts = gelu(x @ W_in^T), fp32 out
    gemm_f16_g<true><<<dim3(8, 16), 256, GA_SMEM>>>(
        d_xf16, d_wf16, nullptr, d_acts, nullptr, DMODEL, FF, 8);       // 2

    gemm_nvproj<<<dim3(FF / 64, DH / 128), 256>>>(nv, phi_w1);          // 3
    prep_misc<<<FF + 1 + 64 + 512, 256>>>(phi_b1, phi_w1);              // 4

    cudaFuncSetAttribute(node_eval, cudaFuncAttributeMaxDynamicSharedMemorySize,
                         NE_SMEM);
    node_eval<<<16 * NQ, 256, NE_SMEM>>>(phi_b1, phi_w1, ln1g, ln1b,
                                         phi_b2, ln2g, ln2b);           // 5

    cheb_transform<<<FF, 256>>>();                                      // 6

    cudaFuncSetAttribute(gemm_final, cudaFuncAttributeMaxDynamicSharedMemorySize,
                         FG_SMEM);
    gemm_final<<<128, 256, FG_SMEM>>>();                                // 7

    ln256_kernel<<<TOK, 256>>>(rln_g, rln_b);                           // 8

    // r2 = gelu(r @ rho_w1^T + b1), fp16 out
    gemm_f16_g<true><<<dim3(8, 4), 256, GA_SMEM>>>(
        d_rf16, d_rw1, rho_b1, nullptr, d_r2f16, DH, DH2, 4);           // 9

    // out = r2 @ rho_w2^T + b2, fp32 out
    gemm_f16_g<false><<<dim3(8, 4), 256, GA_SMEM>>>(
        d_r2f16, d_rw2, rho_b2, out, nullptr, DH2, DMODEL, 8);          // 10

    (void)in_sizes; (void)n_in; (void)out_size;
}